// round 11
// baseline (speedup 1.0000x reference)
#include <cuda_runtime.h>
#include <cuda_bf16.h>
#include <cuda_fp16.h>
#include <cstdint>
#include <math.h>

#define EMAX   250000
#define DEDGE  128
#define DTRI   64

// fp16 intermediates (gather-heavy / round-trip -> keep small)
static __device__ __align__(16) __half g_T  [EMAX * DTRI];
static __device__ __align__(16) __half g_Z  [EMAX * DEDGE];
static __device__ __align__(16) __half g_XST[EMAX * DEDGE];
// bf16 hi/lo activations
static __device__ __align__(16) __nv_bfloat16 g_Xh  [EMAX * DTRI];
static __device__ __align__(16) __nv_bfloat16 g_Xl  [EMAX * DTRI];
// bf16 hi/lo transposed weights [N][K]
static __device__ __align__(16) __nv_bfloat16 g_Wmrh [128 * 128], g_Wmrl [128 * 128];
static __device__ __align__(16) __nv_bfloat16 g_Wmch [64 * 128],  g_Wmcl [64 * 128];
static __device__ __align__(16) __nv_bfloat16 g_Wdh  [128 * 64],  g_Wdl  [128 * 64];
static __device__ __align__(16) __nv_bfloat16 g_Wsth [128 * 128], g_Wstl [128 * 128];
static __device__ __align__(16) __nv_bfloat16 g_Wtsh [128 * 128], g_Wtsl [128 * 128];

#define INV_SQRT_2  0.70710678118654752440f
#define INV_SQRT_NB 0.35355339059327376220f

__device__ __forceinline__ float silu_f(float x) {
    return x / (1.0f + __expf(-x));
}
__device__ __forceinline__ uint32_t smem_u32(const void* p) {
    uint32_t a;
    asm("{ .reg .u64 t; cvta.to.shared.u64 t, %1; cvt.u32.u64 %0, t; }" : "=r"(a) : "l"(p));
    return a;
}
__device__ __forceinline__ void cp_async16(uint32_t dst, const void* src, bool v) {
    int sz = v ? 16 : 0;
    asm volatile("cp.async.cg.shared.global [%0], [%1], 16, %2;"
                 :: "r"(dst), "l"(src), "r"(sz));
}
#define CP_COMMIT() asm volatile("cp.async.commit_group;" ::: "memory")
template<int n> __device__ __forceinline__ void cp_wait() {
    asm volatile("cp.async.wait_group %0;" :: "n"(n) : "memory");
}
__device__ __forceinline__ void ldsm4(uint32_t addr, uint32_t& r0, uint32_t& r1,
                                      uint32_t& r2, uint32_t& r3) {
    asm volatile("ldmatrix.sync.aligned.m8n8.x4.shared.b16 {%0,%1,%2,%3}, [%4];"
                 : "=r"(r0), "=r"(r1), "=r"(r2), "=r"(r3) : "r"(addr));
}
__device__ __forceinline__ void mma_bf16(float* c, const uint32_t* a,
                                         uint32_t b0, uint32_t b1) {
    asm volatile(
        "mma.sync.aligned.m16n8k16.row.col.f32.bf16.bf16.f32 "
        "{%0,%1,%2,%3}, {%4,%5,%6,%7}, {%8,%9}, {%0,%1,%2,%3};"
        : "+f"(c[0]), "+f"(c[1]), "+f"(c[2]), "+f"(c[3])
        : "r"(a[0]), "r"(a[1]), "r"(a[2]), "r"(a[3]), "r"(b0), "r"(b1));
}
__device__ __forceinline__ void split1(float v, __nv_bfloat16& h, __nv_bfloat16& l) {
    h = __float2bfloat16(v);
    l = __float2bfloat16(v - __bfloat162float(h));
}
__device__ __forceinline__ uint32_t pack2(__nv_bfloat16 a, __nv_bfloat16 b) {
    __nv_bfloat162 p; p.x = a; p.y = b;
    return *(uint32_t*)&p;
}
__device__ __forceinline__ void split_pack(float2 v, uint32_t& H, uint32_t& L) {
    __nv_bfloat16 hx, lx, hy, ly;
    split1(v.x, hx, lx); split1(v.y, hy, ly);
    H = pack2(hx, hy); L = pack2(lx, ly);
}

// ---------------- setup: weight transpose-splits (one launch) ----------------
__global__ void split_w_all(
    const float* __restrict__ s0, __nv_bfloat16* __restrict__ d0h, __nv_bfloat16* __restrict__ d0l,
    const float* __restrict__ s1, __nv_bfloat16* __restrict__ d1h, __nv_bfloat16* __restrict__ d1l,
    const float* __restrict__ s2, __nv_bfloat16* __restrict__ d2h, __nv_bfloat16* __restrict__ d2l,
    const float* __restrict__ s3, __nv_bfloat16* __restrict__ d3h, __nv_bfloat16* __restrict__ d3l,
    const float* __restrict__ s4, __nv_bfloat16* __restrict__ d4h, __nv_bfloat16* __restrict__ d4l)
{
    int i = blockIdx.x * blockDim.x + threadIdx.x;
    int w = blockIdx.y;
    const float* src; __nv_bfloat16 *dh, *dl; int K, N;
    switch (w) {
        case 0: src = s0; dh = d0h; dl = d0l; K = 128; N = 128; break;
        case 1: src = s1; dh = d1h; dl = d1l; K = 128; N = 64;  break;
        case 2: src = s2; dh = d2h; dl = d2l; K = 64;  N = 128; break;
        case 3: src = s3; dh = d3h; dl = d3l; K = 128; N = 128; break;
        default: src = s4; dh = d4h; dl = d4l; K = 128; N = 128; break;
    }
    if (i >= K * N) return;
    int k = i / N, n = i % N;
    __nv_bfloat16 h, l;
    split1(src[i], h, l);
    dh[n * K + k] = h;
    dl[n * K + k] = l;
}

// ---------------- chained GEMM ----------------
// Phase1: P = silu(A @ B1^T) [* R(rbf@Wrbf fp32 in epilogue)] -> smem slabs
//   CONVA: A is fp32 in gmem, staged via cp.async into smem scratch, converted in-kernel.
// Phase2: out2(fp16) = silu(P @ B2^T)
// Phase3 (if THREE): out3(fp16) = silu(P @ B3^T)
template<int K1, int N2, bool HAS_R, bool THREE, bool CONVA>
__global__ void __launch_bounds__(256, 2)
gemm_chain(const float* __restrict__ Af32,
           const __nv_bfloat16* __restrict__ Ah, const __nv_bfloat16* __restrict__ Al,
           const __nv_bfloat16* __restrict__ B1h, const __nv_bfloat16* __restrict__ B1l,
           const float* __restrict__ rbf_g, const float* __restrict__ Wrbf_g,
           const __nv_bfloat16* __restrict__ B2h, const __nv_bfloat16* __restrict__ B2l,
           __half* __restrict__ out2,
           const __nv_bfloat16* __restrict__ B3h, const __nv_bfloat16* __restrict__ B3l,
           __half* __restrict__ out3, int M)
{
    constexpr int N1  = 128;
    constexpr int ST  = 40;
    constexpr int NCH1 = (K1 + 31) / 32;
    constexpr uint32_t OFF_AL = 128 * ST * 2;           // 10240
    constexpr uint32_t OFF_BH = 2 * 128 * ST * 2;       // 20480
    constexpr uint32_t SSZ    = OFF_BH + 2 * N1 * ST * 2;  // 40960
    constexpr uint32_t SLAB   = 128 * ST * 2 * 2;       // 20480
    constexpr uint32_t B2OFF  = 2 * SSZ;                // 81920
    constexpr uint32_t STGOFF = B2OFF;                  // fp32 A staging aliases B2 area
    constexpr uint32_t WOFF   = CONVA ? (B2OFF + 16384) : (B2OFF + 2u * N2 * ST * 2);
    constexpr int NT2   = N2 / 16;
    constexpr int NPAIR2 = NT2 / 2;

    extern __shared__ __align__(16) char smu[];
    const uint32_t sbase = smem_u32(smu);

    const int tid  = threadIdx.x;
    const int warp = tid >> 5, lane = tid & 31;
    const int g = lane >> 2, t = lane & 3;
    const int warpM = warp & 3, warpN = warp >> 2;
    const int m0 = warpM * 32;
    const int n0 = warpN * 64;
    const int n0b = warpN * (N2 / 2);
    const int blockRow = blockIdx.x * 128;

    const int lr  = lane & 7;
    const int rowA_base = m0 + lr + ((lane >> 3) & 1) * 8;
    const int kA_off    = (lane >> 4) * 8;
    const int rowB_base = n0 + lr + (lane >> 4) * 8;
    const int rowB2_base = n0b + lr + (lane >> 4) * 8;
    const int kB_off    = ((lane >> 3) & 1) * 8;

    // ======== phase 1 ========
    {
        float acc[2][8][4];
        #pragma unroll
        for (int mt = 0; mt < 2; mt++)
            #pragma unroll
            for (int nt = 0; nt < 8; nt++)
                #pragma unroll
                for (int j = 0; j < 4; j++) acc[mt][nt][j] = 0.0f;

        // B chunk loader (bf16 hi/lo -> stage B region)
        auto loadB = [&](int kb, int stage) {
            const int k0 = kb * 32;
            const uint32_t sb = sbase + (uint32_t)stage * SSZ;
            #pragma unroll
            for (int j = 0; j < 2; j++) {
                int gg = tid + j * 256;
                int n = gg >> 2, q = gg & 3;
                bool v = (k0 + q * 8 < K1);
                size_t so = (size_t)n * K1 + k0 + q * 8;
                uint32_t d = sb + OFF_BH + (uint32_t)(n * ST + q * 8) * 2;
                cp_async16(d, v ? (B1h + so) : B1h, v);
                cp_async16(d + (uint32_t)(N1 * ST * 2), v ? (B1l + so) : B1l, v);
            }
        };
        // A chunk loaders
        auto loadA_bf16 = [&](int kb, int stage) {
            const int k0 = kb * 32;
            const uint32_t sb = sbase + (uint32_t)stage * SSZ;
            #pragma unroll
            for (int j = 0; j < 2; j++) {
                int gg = tid + j * 256;
                int row = gg >> 2, q = gg & 3;
                bool v = (blockRow + row < M) && (k0 + q * 8 < K1);
                size_t so = (size_t)(blockRow + row) * K1 + k0 + q * 8;
                uint32_t d = sb + (uint32_t)(row * ST + q * 8) * 2;
                cp_async16(d, v ? (Ah + so) : Ah, v);
                cp_async16(d + OFF_AL, v ? (Al + so) : Al, v);
            }
        };
        auto loadA_f32 = [&](int kb) {
            const int k0 = kb * 32;
            #pragma unroll
            for (int j = 0; j < 4; j++) {
                int gg = tid + j * 256;              // 1024 granules
                int row = gg >> 3, q = gg & 7;       // 8 granules (32 floats) per row
                bool v = (blockRow + row < M);
                const float* src = v ? (Af32 + (size_t)(blockRow + row) * K1 + k0 + q * 4)
                                     : Af32;
                cp_async16(sbase + STGOFF + (uint32_t)gg * 16, src, v);
            }
        };
        // convert fp32 staging -> bf16 hi/lo stage-A region
        auto convertA = [&](int stage) {
            const uint32_t sb = sbase + (uint32_t)stage * SSZ;
            #pragma unroll
            for (int j = 0; j < 4; j++) {
                int gg = tid + j * 256;
                int row = gg >> 3, q = gg & 7;
                float4 v = *(const float4*)(smu + STGOFF + (uint32_t)gg * 16);
                uint32_t H0, L0, H1, L1;
                split_pack(make_float2(v.x, v.y), H0, L0);
                split_pack(make_float2(v.z, v.w), H1, L1);
                uint32_t off = (uint32_t)(row * ST + q * 4) * 2;
                uint2 Hp; Hp.x = H0; Hp.y = H1;
                uint2 Lp; Lp.x = L0; Lp.y = L1;
                *(uint2*)((char*)smu + (sb - sbase) + off)          = Hp;
                *(uint2*)((char*)smu + (sb - sbase) + OFF_AL + off) = Lp;
            }
        };
        // mma compute on one stage
        auto compute = [&](int stage) {
            const uint32_t sb = sbase + (uint32_t)stage * SSZ;
            #pragma unroll
            for (int ks = 0; ks < 2; ks++) {
                uint32_t ah[2][4], al[2][4];
                #pragma unroll
                for (int mt = 0; mt < 2; mt++) {
                    uint32_t ea = (uint32_t)((rowA_base + mt * 16) * ST + ks * 16 + kA_off) * 2;
                    ldsm4(sb + ea,          ah[mt][0], ah[mt][1], ah[mt][2], ah[mt][3]);
                    ldsm4(sb + OFF_AL + ea, al[mt][0], al[mt][1], al[mt][2], al[mt][3]);
                }
                #pragma unroll
                for (int p = 0; p < 4; p++) {
                    uint32_t eb = (uint32_t)((rowB_base + p * 16) * ST + ks * 16 + kB_off) * 2;
                    uint32_t bh0, bh1, bh2, bh3, bl0, bl1, bl2, bl3;
                    ldsm4(sb + OFF_BH + eb, bh0, bh1, bh2, bh3);
                    ldsm4(sb + OFF_BH + (uint32_t)(N1 * ST * 2) + eb, bl0, bl1, bl2, bl3);
                    #pragma unroll
                    for (int mt = 0; mt < 2; mt++) {
                        float* c0 = acc[mt][2 * p];
                        float* c1 = acc[mt][2 * p + 1];
                        mma_bf16(c0, ah[mt], bh0, bh1);
                        mma_bf16(c0, ah[mt], bl0, bl1);
                        mma_bf16(c0, al[mt], bh0, bh1);
                        mma_bf16(c1, ah[mt], bh2, bh3);
                        mma_bf16(c1, ah[mt], bl2, bl3);
                        mma_bf16(c1, al[mt], bh2, bh3);
                    }
                }
            }
        };

        if (HAS_R) {
            #pragma unroll
            for (int j = 0; j < 2; j++) {
                int q = tid + j * 256;
                cp_async16(sbase + WOFF + (uint32_t)q * 16, Wrbf_g + q * 4, true);
            }
        }

        if (CONVA) {
            loadA_f32(0); loadB(0, 0); CP_COMMIT();
            cp_wait<0>();
            __syncthreads();
            for (int kb = 0; kb < NCH1; kb++) {
                convertA(kb & 1);
                __syncthreads();
                if (kb + 1 < NCH1) {
                    loadA_f32(kb + 1);
                    loadB(kb + 1, (kb + 1) & 1);
                    CP_COMMIT();
                }
                compute(kb & 1);
                if (kb + 1 < NCH1) cp_wait<0>();
                __syncthreads();
            }
        } else {
            loadA_bf16(0, 0); loadB(0, 0); CP_COMMIT();
            for (int kb = 0; kb < NCH1; kb++) {
                if (kb + 1 < NCH1) {
                    loadA_bf16(kb + 1, (kb + 1) & 1);
                    loadB(kb + 1, (kb + 1) & 1);
                    CP_COMMIT();
                    cp_wait<1>();
                } else {
                    cp_wait<0>();
                }
                __syncthreads();
                compute(kb & 1);
                __syncthreads();
            }
        }

        // epilogue 1: silu [* R], split -> slabs
        const float2* Wsm2 = (const float2*)(smu + WOFF);
        #pragma unroll
        for (int mt = 0; mt < 2; mt++) {
            int row0 = m0 + mt * 16 + g;
            int row1 = row0 + 8;
            int gr0 = blockRow + row0, gr1 = blockRow + row1;
            float rb0[16], rb1[16];
            if (HAS_R) {
                #pragma unroll
                for (int q = 0; q < 4; q++) {
                    float4 v0 = make_float4(0.f, 0.f, 0.f, 0.f);
                    float4 v1 = make_float4(0.f, 0.f, 0.f, 0.f);
                    if (gr0 < M) v0 = *(const float4*)(rbf_g + (size_t)gr0 * 16 + q * 4);
                    if (gr1 < M) v1 = *(const float4*)(rbf_g + (size_t)gr1 * 16 + q * 4);
                    rb0[q * 4 + 0] = v0.x; rb0[q * 4 + 1] = v0.y;
                    rb0[q * 4 + 2] = v0.z; rb0[q * 4 + 3] = v0.w;
                    rb1[q * 4 + 0] = v1.x; rb1[q * 4 + 1] = v1.y;
                    rb1[q * 4 + 2] = v1.z; rb1[q * 4 + 3] = v1.w;
                }
            }
            #pragma unroll
            for (int nt = 0; nt < 8; nt++) {
                int cc = n0 + nt * 8 + 2 * t;
                float r00 = 1.f, r01 = 1.f, r10 = 1.f, r11 = 1.f;
                if (HAS_R) {
                    r00 = r01 = r10 = r11 = 0.f;
                    #pragma unroll
                    for (int k = 0; k < 16; k++) {
                        float2 w = Wsm2[k * 64 + (cc >> 1)];
                        r00 = fmaf(rb0[k], w.x, r00); r01 = fmaf(rb0[k], w.y, r01);
                        r10 = fmaf(rb1[k], w.x, r10); r11 = fmaf(rb1[k], w.y, r11);
                    }
                }
                float v00 = silu_f(acc[mt][nt][0]) * r00;
                float v01 = silu_f(acc[mt][nt][1]) * r01;
                float v10 = silu_f(acc[mt][nt][2]) * r10;
                float v11 = silu_f(acc[mt][nt][3]) * r11;
                if (gr0 >= M) { v00 = 0.f; v01 = 0.f; }
                if (gr1 >= M) { v10 = 0.f; v11 = 0.f; }
                uint32_t H0, L0, H1, L1;
                split_pack(make_float2(v00, v01), H0, L0);
                split_pack(make_float2(v10, v11), H1, L1);
                uint32_t chunk = (uint32_t)(cc >> 5);
                uint32_t off0 = (uint32_t)(row0 * ST + (cc & 31)) * 2;
                uint32_t off1 = (uint32_t)(row1 * ST + (cc & 31)) * 2;
                *(uint32_t*)(smu + chunk * SLAB + off0)          = H0;
                *(uint32_t*)(smu + chunk * SLAB + OFF_AL + off0) = L0;
                *(uint32_t*)(smu + chunk * SLAB + off1)          = H1;
                *(uint32_t*)(smu + chunk * SLAB + OFF_AL + off1) = L1;
            }
        }
        __syncthreads();
    }

    // ======== phase 2 (+3): silu(P @ B^T) -> fp16, K = 128 ========
    const uint32_t b2base = sbase + B2OFF;
    #pragma unroll
    for (int ph = 0; ph < (THREE ? 2 : 1); ph++) {
        const __nv_bfloat16* Bh = (ph == 0) ? B2h : B3h;
        const __nv_bfloat16* Bl = (ph == 0) ? B2l : B3l;
        __half* outp = (ph == 0) ? out2 : out3;

        float acc2[2][NT2][4];
        #pragma unroll
        for (int mt = 0; mt < 2; mt++)
            #pragma unroll
            for (int nt = 0; nt < NT2; nt++)
                #pragma unroll
                for (int j = 0; j < 4; j++) acc2[mt][nt][j] = 0.0f;

        for (int kb = 0; kb < 4; kb++) {
            #pragma unroll
            for (int j = 0; j < (N2 * 4) / 256; j++) {
                int gg = tid + j * 256;
                int n = gg >> 2, q = gg & 3;
                size_t so = (size_t)n * 128 + kb * 32 + q * 8;
                uint32_t d = b2base + (uint32_t)(n * ST + q * 8) * 2;
                cp_async16(d, Bh + so, true);
                cp_async16(d + (uint32_t)(N2 * ST * 2), Bl + so, true);
            }
            CP_COMMIT();
            cp_wait<0>();
            __syncthreads();

            const uint32_t slab = sbase + (uint32_t)kb * SLAB;
            #pragma unroll
            for (int ks = 0; ks < 2; ks++) {
                uint32_t ah[2][4], al[2][4];
                #pragma unroll
                for (int mt = 0; mt < 2; mt++) {
                    uint32_t ea = (uint32_t)((rowA_base + mt * 16) * ST + ks * 16 + kA_off) * 2;
                    ldsm4(slab + ea,          ah[mt][0], ah[mt][1], ah[mt][2], ah[mt][3]);
                    ldsm4(slab + OFF_AL + ea, al[mt][0], al[mt][1], al[mt][2], al[mt][3]);
                }
                #pragma unroll
                for (int p = 0; p < NPAIR2; p++) {
                    uint32_t eb = (uint32_t)((rowB2_base + p * 16) * ST + ks * 16 + kB_off) * 2;
                    uint32_t bh0, bh1, bh2, bh3, bl0, bl1, bl2, bl3;
                    ldsm4(b2base + eb, bh0, bh1, bh2, bh3);
                    ldsm4(b2base + (uint32_t)(N2 * ST * 2) + eb, bl0, bl1, bl2, bl3);
                    #pragma unroll
                    for (int mt = 0; mt < 2; mt++) {
                        float* c0 = acc2[mt][2 * p];
                        float* c1 = acc2[mt][2 * p + 1];
                        mma_bf16(c0, ah[mt], bh0, bh1);
                        mma_bf16(c0, ah[mt], bl0, bl1);
                        mma_bf16(c0, al[mt], bh0, bh1);
                        mma_bf16(c1, ah[mt], bh2, bh3);
                        mma_bf16(c1, ah[mt], bl2, bl3);
                        mma_bf16(c1, al[mt], bh2, bh3);
                    }
                }
            }
            __syncthreads();
        }

        #pragma unroll
        for (int mt = 0; mt < 2; mt++) {
            #pragma unroll
            for (int half = 0; half < 2; half++) {
                int r = blockRow + m0 + mt * 16 + g + half * 8;
                if (r >= M) continue;
                #pragma unroll
                for (int nt = 0; nt < NT2; nt++) {
                    int cc = n0b + nt * 8 + 2 * t;
                    float v0 = silu_f(acc2[mt][nt][half * 2 + 0]);
                    float v1 = silu_f(acc2[mt][nt][half * 2 + 1]);
                    ((__half2*)outp)[(size_t)r * (N2 / 2) + (cc >> 1)] =
                        __floats2half2_rn(v0, v1);
                }
            }
        }
        if (THREE && ph == 0) __syncthreads();
    }
}

// ---------------- triplet (FFMA, fp16 T) ----------------
__global__ void __launch_bounds__(256)
triplet_kernel(const __half* __restrict__ T, const float* __restrict__ cbf,
               const int* __restrict__ idx_s, const int* __restrict__ basis,
               const float* __restrict__ Wc,
               __nv_bfloat16* __restrict__ Xh, __nv_bfloat16* __restrict__ Xl, int E)
{
    __shared__ float cb[8][128];
    const int warp = threadIdx.x >> 5;
    const int lane = threadIdx.x & 31;

    float w0[16], w1[16];
    #pragma unroll
    for (int c = 0; c < 16; c++) {
        w0[c] = Wc[c * 64 + 2 * lane];
        w1[c] = Wc[c * 64 + 2 * lane + 1];
    }

    const __half2* T2 = (const __half2*)T;
    const int gw = blockIdx.x * 8 + warp;
    const int nwarps = gridDim.x * 8;

    for (int e = gw; e < E; e += nwarps) {
        int s = idx_s[e];
        int b1v = 0;
        if (lane < 8) b1v = basis[s * 8 + lane];

        float4 v = *(const float4*)(cbf + (size_t)e * 128 + lane * 4);
        *(float4*)(&cb[warp][lane * 4]) = v;
        __syncwarp();

        int bidx[8];
        #pragma unroll
        for (int nb = 0; nb < 8; nb++)
            bidx[nb] = __shfl_sync(0xffffffffu, b1v, nb);

        __half2 tv[8];
        #pragma unroll
        for (int nb = 0; nb < 8; nb++)
            tv[nb] = T2[(size_t)bidx[nb] * 32 + lane];

        float acc0 = 0.f, acc1 = 0.f;
        #pragma unroll
        for (int nb = 0; nb < 8; nb++) {
            float d0 = 0.f, d1 = 0.f;
            #pragma unroll
            for (int c = 0; c < 16; c++) {
                float a = cb[warp][nb * 16 + c];
                d0 = fmaf(a, w0[c], d0);
                d1 = fmaf(a, w1[c], d1);
            }
            float2 tt = __half22float2(tv[nb]);
            acc0 = fmaf(tt.x, d0, acc0);
            acc1 = fmaf(tt.y, d1, acc1);
        }
        uint32_t H, L;
        split_pack(make_float2(acc0 * INV_SQRT_NB, acc1 * INV_SQRT_NB), H, L);
        ((uint32_t*)Xh)[(size_t)e * 32 + lane] = H;
        ((uint32_t*)Xl)[(size_t)e * 32 + lane] = L;
        __syncwarp();
    }
}

// ---------------- final elementwise: out = (XST + Z[swap]) * c ----------------
__global__ void __launch_bounds__(256)
final_ew(const __half* __restrict__ XST, const __half* __restrict__ Z,
         const int* __restrict__ swp, float* __restrict__ out, int E)
{
    size_t total = (size_t)E * 16;
    size_t stride = (size_t)gridDim.x * blockDim.x;
    for (size_t i = (size_t)blockIdx.x * blockDim.x + threadIdx.x; i < total; i += stride) {
        size_t e = i >> 4;
        int    q = (int)(i & 15);
        int    s = swp[e];
        uint4 a = ((const uint4*)XST)[i];
        uint4 b = ((const uint4*)Z)[(size_t)s * 16 + q];
        const __half2* ah = (const __half2*)&a;
        const __half2* bh = (const __half2*)&b;
        float4 o0, o1;
        float2 r0 = __half22float2(ah[0]), z0 = __half22float2(bh[0]);
        float2 r1 = __half22float2(ah[1]), z1 = __half22float2(bh[1]);
        float2 r2 = __half22float2(ah[2]), z2 = __half22float2(bh[2]);
        float2 r3 = __half22float2(ah[3]), z3 = __half22float2(bh[3]);
        o0.x = (r0.x + z0.x) * INV_SQRT_2; o0.y = (r0.y + z0.y) * INV_SQRT_2;
        o0.z = (r1.x + z1.x) * INV_SQRT_2; o0.w = (r1.y + z1.y) * INV_SQRT_2;
        o1.x = (r2.x + z2.x) * INV_SQRT_2; o1.y = (r2.y + z2.y) * INV_SQRT_2;
        o1.z = (r3.x + z3.x) * INV_SQRT_2; o1.w = (r3.y + z3.y) * INV_SQRT_2;
        ((float4*)out)[e * 32 + q * 2]     = o0;
        ((float4*)out)[e * 32 + q * 2 + 1] = o1;
    }
}

extern "C" void kernel_launch(void* const* d_in, const int* in_sizes, int n_in,
                              void* d_out, int out_size)
{
    const float* m_st     = (const float*)d_in[0];
    const float* rbf      = (const float*)d_in[1];
    const float* cbf      = (const float*)d_in[2];
    const int*   idx_s    = (const int*)d_in[3];
    const int*   idx_swap = (const int*)d_in[4];
    const int*   basis    = (const int*)d_in[5];
    const float* W_m_rbf  = (const float*)d_in[6];
    const float* W_rbf    = (const float*)d_in[7];
    const float* W_m_cbf  = (const float*)d_in[8];
    const float* W_cbf    = (const float*)d_in[9];
    const float* W_dir    = (const float*)d_in[10];
    const float* W_st     = (const float*)d_in[11];
    const float* W_ts     = (const float*)d_in[12];
    float* out = (float*)d_out;

    const int E = in_sizes[0] / DEDGE;

    __half *pT, *pZ, *pXST;
    __nv_bfloat16 *pXh, *pXl;
    __nv_bfloat16 *wmrh, *wmrl, *wmch, *wmcl, *wdh, *wdl, *wsth, *wstl, *wtsh, *wtsl;
    cudaGetSymbolAddress((void**)&pT,   g_T);
    cudaGetSymbolAddress((void**)&pZ,   g_Z);
    cudaGetSymbolAddress((void**)&pXST, g_XST);
    cudaGetSymbolAddress((void**)&pXh,  g_Xh);    cudaGetSymbolAddress((void**)&pXl, g_Xl);
    cudaGetSymbolAddress((void**)&wmrh, g_Wmrh);  cudaGetSymbolAddress((void**)&wmrl, g_Wmrl);
    cudaGetSymbolAddress((void**)&wmch, g_Wmch);  cudaGetSymbolAddress((void**)&wmcl, g_Wmcl);
    cudaGetSymbolAddress((void**)&wdh,  g_Wdh);   cudaGetSymbolAddress((void**)&wdl, g_Wdl);
    cudaGetSymbolAddress((void**)&wsth, g_Wsth);  cudaGetSymbolAddress((void**)&wstl, g_Wstl);
    cudaGetSymbolAddress((void**)&wtsh, g_Wtsh);  cudaGetSymbolAddress((void**)&wtsl, g_Wtsl);

    const int gB = (E + 127) / 128;

    const int smem_f12 = 81920 + 16384 + 8192;   // stages + fp32 staging + Wrbf = 106496
    const int smem_f45 = 81920 + 2 * 128 * 40 * 2;  // 102400

    cudaFuncSetAttribute(gemm_chain<128, 64, true, false, true>,
                         cudaFuncAttributeMaxDynamicSharedMemorySize, smem_f12);
    cudaFuncSetAttribute(gemm_chain<64, 128, false, true, false>,
                         cudaFuncAttributeMaxDynamicSharedMemorySize, smem_f45);

    // launch 0: split all 5 weights
    {
        dim3 grid(64, 5);
        split_w_all<<<grid, 256>>>(
            W_m_rbf, wmrh, wmrl,
            W_m_cbf, wmch, wmcl,
            W_dir,   wdh,  wdl,
            W_st,    wsth, wstl,
            W_ts,    wtsh, wtsl);
    }
    // launch 1 (F12): M1 = silu(m_st@W_m_rbf) * (rbf@W_rbf) -> T(fp16) = silu(M1@W_m_cbf)
    //   m_st read as fp32, split in-kernel.
    gemm_chain<128, 64, true, false, true><<<gB, 256, smem_f12>>>(
        m_st, nullptr, nullptr, wmrh, wmrl, rbf, W_rbf, wmch, wmcl, pT,
        nullptr, nullptr, nullptr, E);
    // launch 2: triplet -> X bf16 hi/lo
    triplet_kernel<<<2048, 256>>>(pT, cbf, idx_s, basis, W_cbf, pXh, pXl, E);
    // launch 3 (F45, 3-phase): Y = silu(X@W_dir) (smem) -> Z(fp16)=silu(Y@W_ts), XST(fp16)=silu(Y@W_st)
    gemm_chain<64, 128, false, true, false><<<gB, 256, smem_f45>>>(
        nullptr, pXh, pXl, wdh, wdl, nullptr, nullptr, wtsh, wtsl, pZ,
        wsth, wstl, pXST, E);
    // launch 4: out = (XST + Z[idx_swap]) * INV_SQRT_2
    final_ew<<<4096, 256>>>(pXST, pZ, idx_swap, out, E);
}

// round 12
// speedup vs baseline: 1.4175x; 1.4175x over previous
#include <cuda_runtime.h>
#include <cuda_bf16.h>
#include <cuda_fp16.h>
#include <cstdint>
#include <math.h>

#define EMAX   250000
#define DEDGE  128
#define DTRI   64

// fp16 intermediates (gather-heavy / round-trip -> keep small)
static __device__ __align__(16) __half g_T  [EMAX * DTRI];
static __device__ __align__(16) __half g_Z  [EMAX * DEDGE];
static __device__ __align__(16) __half g_XST[EMAX * DEDGE];
// bf16 hi/lo pre-split activations
static __device__ __align__(16) __nv_bfloat16 g_msth[EMAX * DEDGE];
static __device__ __align__(16) __nv_bfloat16 g_mstl[EMAX * DEDGE];
static __device__ __align__(16) __nv_bfloat16 g_Xh  [EMAX * DTRI];
static __device__ __align__(16) __nv_bfloat16 g_Xl  [EMAX * DTRI];
// bf16 hi/lo transposed weights [N][K]
static __device__ __align__(16) __nv_bfloat16 g_Wmrh [128 * 128], g_Wmrl [128 * 128];
static __device__ __align__(16) __nv_bfloat16 g_Wmch [64 * 128],  g_Wmcl [64 * 128];
static __device__ __align__(16) __nv_bfloat16 g_Wdh  [128 * 64],  g_Wdl  [128 * 64];
static __device__ __align__(16) __nv_bfloat16 g_Wsth [128 * 128], g_Wstl [128 * 128];
static __device__ __align__(16) __nv_bfloat16 g_Wtsh [128 * 128], g_Wtsl [128 * 128];

#define INV_SQRT_2  0.70710678118654752440f
#define INV_SQRT_NB 0.35355339059327376220f

__device__ __forceinline__ float silu_f(float x) {
    return x / (1.0f + __expf(-x));
}
__device__ __forceinline__ uint32_t smem_u32(const void* p) {
    uint32_t a;
    asm("{ .reg .u64 t; cvta.to.shared.u64 t, %1; cvt.u32.u64 %0, t; }" : "=r"(a) : "l"(p));
    return a;
}
__device__ __forceinline__ void cp_async16(uint32_t dst, const void* src, bool v) {
    int sz = v ? 16 : 0;
    asm volatile("cp.async.cg.shared.global [%0], [%1], 16, %2;"
                 :: "r"(dst), "l"(src), "r"(sz));
}
#define CP_COMMIT() asm volatile("cp.async.commit_group;" ::: "memory")
template<int n> __device__ __forceinline__ void cp_wait() {
    asm volatile("cp.async.wait_group %0;" :: "n"(n) : "memory");
}
__device__ __forceinline__ void ldsm4(uint32_t addr, uint32_t& r0, uint32_t& r1,
                                      uint32_t& r2, uint32_t& r3) {
    asm volatile("ldmatrix.sync.aligned.m8n8.x4.shared.b16 {%0,%1,%2,%3}, [%4];"
                 : "=r"(r0), "=r"(r1), "=r"(r2), "=r"(r3) : "r"(addr));
}
__device__ __forceinline__ void mma_bf16(float* c, const uint32_t* a,
                                         uint32_t b0, uint32_t b1) {
    asm volatile(
        "mma.sync.aligned.m16n8k16.row.col.f32.bf16.bf16.f32 "
        "{%0,%1,%2,%3}, {%4,%5,%6,%7}, {%8,%9}, {%0,%1,%2,%3};"
        : "+f"(c[0]), "+f"(c[1]), "+f"(c[2]), "+f"(c[3])
        : "r"(a[0]), "r"(a[1]), "r"(a[2]), "r"(a[3]), "r"(b0), "r"(b1));
}
__device__ __forceinline__ void split1(float v, __nv_bfloat16& h, __nv_bfloat16& l) {
    h = __float2bfloat16(v);
    l = __float2bfloat16(v - __bfloat162float(h));
}
__device__ __forceinline__ uint32_t pack2(__nv_bfloat16 a, __nv_bfloat16 b) {
    __nv_bfloat162 p; p.x = a; p.y = b;
    return *(uint32_t*)&p;
}
__device__ __forceinline__ void split_pack(float2 v, uint32_t& H, uint32_t& L) {
    __nv_bfloat16 hx, lx, hy, ly;
    split1(v.x, hx, lx); split1(v.y, hy, ly);
    H = pack2(hx, hy); L = pack2(lx, ly);
}

// ---------------- setup split kernels ----------------
__global__ void split_rows(const float* __restrict__ src,
                           __nv_bfloat16* __restrict__ dh,
                           __nv_bfloat16* __restrict__ dl, int n2)
{
    int i = blockIdx.x * blockDim.x + threadIdx.x;
    if (i >= n2) return;
    float2 v = ((const float2*)src)[i];
    uint32_t H, L;
    split_pack(v, H, L);
    ((uint32_t*)dh)[i] = H;
    ((uint32_t*)dl)[i] = L;
}

__global__ void split_w_all(
    const float* __restrict__ s0, __nv_bfloat16* __restrict__ d0h, __nv_bfloat16* __restrict__ d0l,
    const float* __restrict__ s1, __nv_bfloat16* __restrict__ d1h, __nv_bfloat16* __restrict__ d1l,
    const float* __restrict__ s2, __nv_bfloat16* __restrict__ d2h, __nv_bfloat16* __restrict__ d2l,
    const float* __restrict__ s3, __nv_bfloat16* __restrict__ d3h, __nv_bfloat16* __restrict__ d3l,
    const float* __restrict__ s4, __nv_bfloat16* __restrict__ d4h, __nv_bfloat16* __restrict__ d4l)
{
    int i = blockIdx.x * blockDim.x + threadIdx.x;
    int w = blockIdx.y;
    const float* src; __nv_bfloat16 *dh, *dl; int K, N;
    switch (w) {
        case 0: src = s0; dh = d0h; dl = d0l; K = 128; N = 128; break;
        case 1: src = s1; dh = d1h; dl = d1l; K = 128; N = 64;  break;
        case 2: src = s2; dh = d2h; dl = d2l; K = 64;  N = 128; break;
        case 3: src = s3; dh = d3h; dl = d3l; K = 128; N = 128; break;
        default: src = s4; dh = d4h; dl = d4l; K = 128; N = 128; break;
    }
    if (i >= K * N) return;
    int k = i / N, n = i % N;
    __nv_bfloat16 h, l;
    split1(src[i], h, l);
    dh[n * K + k] = h;
    dl[n * K + k] = l;
}

// ---------------- chained GEMM (2 or 3 phases) ----------------
// Phase1: P = silu(A @ B1^T) [* R(rbf@Wrbf fp32 in epilogue)] -> smem slabs
// Phase2: out2(fp16) = os2 * silu(P @ B2^T)
// Phase3 (if THREE): out3(fp16) = os2 * silu(P @ B3^T)
template<int K1, int N2, bool HAS_R, bool THREE>
__global__ void __launch_bounds__(256, 2)
gemm_chain(const __nv_bfloat16* __restrict__ Ah, const __nv_bfloat16* __restrict__ Al,
           const __nv_bfloat16* __restrict__ B1h, const __nv_bfloat16* __restrict__ B1l,
           const float* __restrict__ rbf_g, const float* __restrict__ Wrbf_g,
           const __nv_bfloat16* __restrict__ B2h, const __nv_bfloat16* __restrict__ B2l,
           __half* __restrict__ out2,
           const __nv_bfloat16* __restrict__ B3h, const __nv_bfloat16* __restrict__ B3l,
           __half* __restrict__ out3, float os2, int M)
{
    constexpr int N1  = 128;
    constexpr int ST  = 40;
    constexpr int NCH1 = (K1 + 31) / 32;
    constexpr uint32_t OFF_AL = 128 * ST * 2;
    constexpr uint32_t OFF_BH = 2 * 128 * ST * 2;
    constexpr uint32_t SSZ    = OFF_BH + 2 * N1 * ST * 2;   // 40960
    constexpr uint32_t SLAB   = 128 * ST * 2 * 2;           // 20480
    constexpr uint32_t B2OFF  = 2 * SSZ;                    // 81920
    constexpr uint32_t WOFF   = B2OFF + 2u * N2 * ST * 2;
    constexpr int NT2   = N2 / 16;
    constexpr int NPAIR2 = NT2 / 2;

    extern __shared__ __align__(16) char smu[];
    const uint32_t sbase = smem_u32(smu);

    const int tid  = threadIdx.x;
    const int warp = tid >> 5, lane = tid & 31;
    const int g = lane >> 2, t = lane & 3;
    const int warpM = warp & 3, warpN = warp >> 2;
    const int m0 = warpM * 32;
    const int n0 = warpN * 64;
    const int n0b = warpN * (N2 / 2);
    const int blockRow = blockIdx.x * 128;

    const int lr  = lane & 7;
    const int rowA_base = m0 + lr + ((lane >> 3) & 1) * 8;
    const int kA_off    = (lane >> 4) * 8;
    const int rowB_base = n0 + lr + (lane >> 4) * 8;
    const int rowB2_base = n0b + lr + (lane >> 4) * 8;
    const int kB_off    = ((lane >> 3) & 1) * 8;

    const uint32_t b2base = sbase + B2OFF;

    // phase-2/3 B chunk loader (commits one group)
    auto loadB2 = [&](const __nv_bfloat16* Bh, const __nv_bfloat16* Bl, int kb) {
        #pragma unroll
        for (int j = 0; j < (N2 * 4) / 256; j++) {
            int gg = tid + j * 256;
            int n = gg >> 2, q = gg & 3;
            size_t so = (size_t)n * 128 + kb * 32 + q * 8;
            uint32_t d = b2base + (uint32_t)(n * ST + q * 8) * 2;
            cp_async16(d, Bh + so, true);
            cp_async16(d + (uint32_t)(N2 * ST * 2), Bl + so, true);
        }
        CP_COMMIT();
    };

    // ======== phase 1 ========
    {
        float acc[2][8][4];
        #pragma unroll
        for (int mt = 0; mt < 2; mt++)
            #pragma unroll
            for (int nt = 0; nt < 8; nt++)
                #pragma unroll
                for (int j = 0; j < 4; j++) acc[mt][nt][j] = 0.0f;

        auto load_chunk = [&](int kb, int stage) {
            const int k0 = kb * 32;
            const uint32_t sb = sbase + (uint32_t)stage * SSZ;
            #pragma unroll
            for (int j = 0; j < 2; j++) {
                int gg = tid + j * 256;
                int row = gg >> 2, q = gg & 3;
                bool v = (blockRow + row < M) && (k0 + q * 8 < K1);
                size_t so = (size_t)(blockRow + row) * K1 + k0 + q * 8;
                uint32_t d = sb + (uint32_t)(row * ST + q * 8) * 2;
                cp_async16(d, v ? (Ah + so) : Ah, v);
                cp_async16(d + OFF_AL, v ? (Al + so) : Al, v);
            }
            #pragma unroll
            for (int j = 0; j < 2; j++) {
                int gg = tid + j * 256;
                int n = gg >> 2, q = gg & 3;
                bool v = (k0 + q * 8 < K1);
                size_t so = (size_t)n * K1 + k0 + q * 8;
                uint32_t d = sb + OFF_BH + (uint32_t)(n * ST + q * 8) * 2;
                cp_async16(d, v ? (B1h + so) : B1h, v);
                cp_async16(d + (uint32_t)(N1 * ST * 2), v ? (B1l + so) : B1l, v);
            }
            CP_COMMIT();
        };

        if (HAS_R) {
            #pragma unroll
            for (int j = 0; j < 2; j++) {
                int q = tid + j * 256;
                cp_async16(sbase + WOFF + (uint32_t)q * 16, Wrbf_g + q * 4, true);
            }
        }
        load_chunk(0, 0);
        for (int kb = 0; kb < NCH1; kb++) {
            if (kb + 1 < NCH1) { load_chunk(kb + 1, (kb + 1) & 1); cp_wait<1>(); }
            else               { cp_wait<0>(); }
            __syncthreads();

            const uint32_t sb = sbase + (uint32_t)(kb & 1) * SSZ;
            #pragma unroll
            for (int ks = 0; ks < 2; ks++) {
                uint32_t ah[2][4], al[2][4];
                #pragma unroll
                for (int mt = 0; mt < 2; mt++) {
                    uint32_t ea = (uint32_t)((rowA_base + mt * 16) * ST + ks * 16 + kA_off) * 2;
                    ldsm4(sb + ea,          ah[mt][0], ah[mt][1], ah[mt][2], ah[mt][3]);
                    ldsm4(sb + OFF_AL + ea, al[mt][0], al[mt][1], al[mt][2], al[mt][3]);
                }
                #pragma unroll
                for (int p = 0; p < 4; p++) {
                    uint32_t eb = (uint32_t)((rowB_base + p * 16) * ST + ks * 16 + kB_off) * 2;
                    uint32_t bh0, bh1, bh2, bh3, bl0, bl1, bl2, bl3;
                    ldsm4(sb + OFF_BH + eb, bh0, bh1, bh2, bh3);
                    ldsm4(sb + OFF_BH + (uint32_t)(N1 * ST * 2) + eb, bl0, bl1, bl2, bl3);
                    #pragma unroll
                    for (int mt = 0; mt < 2; mt++) {
                        float* c0 = acc[mt][2 * p];
                        float* c1 = acc[mt][2 * p + 1];
                        mma_bf16(c0, ah[mt], bh0, bh1);
                        mma_bf16(c0, ah[mt], bl0, bl1);
                        mma_bf16(c0, al[mt], bh0, bh1);
                        mma_bf16(c1, ah[mt], bh2, bh3);
                        mma_bf16(c1, ah[mt], bl2, bl3);
                        mma_bf16(c1, al[mt], bh2, bh3);
                    }
                }
            }
            __syncthreads();
        }

        // preload phase-2 first B chunk (B buffer idle during epilogue 1)
        loadB2(B2h, B2l, 0);

        // epilogue 1: silu [* R], split -> slabs
        const float2* Wsm2 = (const float2*)(smu + WOFF);
        #pragma unroll
        for (int mt = 0; mt < 2; mt++) {
            int row0 = m0 + mt * 16 + g;
            int row1 = row0 + 8;
            int gr0 = blockRow + row0, gr1 = blockRow + row1;
            float rb0[16], rb1[16];
            if (HAS_R) {
                #pragma unroll
                for (int q = 0; q < 4; q++) {
                    float4 v0 = make_float4(0.f, 0.f, 0.f, 0.f);
                    float4 v1 = make_float4(0.f, 0.f, 0.f, 0.f);
                    if (gr0 < M) v0 = *(const float4*)(rbf_g + (size_t)gr0 * 16 + q * 4);
                    if (gr1 < M) v1 = *(const float4*)(rbf_g + (size_t)gr1 * 16 + q * 4);
                    rb0[q * 4 + 0] = v0.x; rb0[q * 4 + 1] = v0.y;
                    rb0[q * 4 + 2] = v0.z; rb0[q * 4 + 3] = v0.w;
                    rb1[q * 4 + 0] = v1.x; rb1[q * 4 + 1] = v1.y;
                    rb1[q * 4 + 2] = v1.z; rb1[q * 4 + 3] = v1.w;
                }
            }
            #pragma unroll
            for (int nt = 0; nt < 8; nt++) {
                int cc = n0 + nt * 8 + 2 * t;
                float r00 = 1.f, r01 = 1.f, r10 = 1.f, r11 = 1.f;
                if (HAS_R) {
                    r00 = r01 = r10 = r11 = 0.f;
                    #pragma unroll
                    for (int k = 0; k < 16; k++) {
                        float2 w = Wsm2[k * 64 + (cc >> 1)];
                        r00 = fmaf(rb0[k], w.x, r00); r01 = fmaf(rb0[k], w.y, r01);
                        r10 = fmaf(rb1[k], w.x, r10); r11 = fmaf(rb1[k], w.y, r11);
                    }
                }
                float v00 = silu_f(acc[mt][nt][0]) * r00;
                float v01 = silu_f(acc[mt][nt][1]) * r01;
                float v10 = silu_f(acc[mt][nt][2]) * r10;
                float v11 = silu_f(acc[mt][nt][3]) * r11;
                if (gr0 >= M) { v00 = 0.f; v01 = 0.f; }
                if (gr1 >= M) { v10 = 0.f; v11 = 0.f; }
                uint32_t H0, L0, H1, L1;
                split_pack(make_float2(v00, v01), H0, L0);
                split_pack(make_float2(v10, v11), H1, L1);
                uint32_t chunk = (uint32_t)(cc >> 5);
                uint32_t off0 = (uint32_t)(row0 * ST + (cc & 31)) * 2;
                uint32_t off1 = (uint32_t)(row1 * ST + (cc & 31)) * 2;
                *(uint32_t*)(smu + chunk * SLAB + off0)          = H0;
                *(uint32_t*)(smu + chunk * SLAB + OFF_AL + off0) = L0;
                *(uint32_t*)(smu + chunk * SLAB + off1)          = H1;
                *(uint32_t*)(smu + chunk * SLAB + OFF_AL + off1) = L1;
            }
        }
        __syncthreads();
    }

    // ======== phase 2 (+3): silu(P @ B^T) * os2 -> fp16, K = 128 ========
    #pragma unroll
    for (int ph = 0; ph < (THREE ? 2 : 1); ph++) {
        const __nv_bfloat16* Bh = (ph == 0) ? B2h : B3h;
        const __nv_bfloat16* Bl = (ph == 0) ? B2l : B3l;
        __half* outp = (ph == 0) ? out2 : out3;

        float acc2[2][NT2][4];
        #pragma unroll
        for (int mt = 0; mt < 2; mt++)
            #pragma unroll
            for (int nt = 0; nt < NT2; nt++)
                #pragma unroll
                for (int j = 0; j < 4; j++) acc2[mt][nt][j] = 0.0f;

        for (int kb = 0; kb < 4; kb++) {
            // chunk kb's B load was committed by the previous iteration (or preloaded)
            cp_wait<0>();
            __syncthreads();

            const uint32_t slab = sbase + (uint32_t)kb * SLAB;
            #pragma unroll
            for (int ks = 0; ks < 2; ks++) {
                uint32_t ah[2][4], al[2][4];
                #pragma unroll
                for (int mt = 0; mt < 2; mt++) {
                    uint32_t ea = (uint32_t)((rowA_base + mt * 16) * ST + ks * 16 + kA_off) * 2;
                    ldsm4(slab + ea,          ah[mt][0], ah[mt][1], ah[mt][2], ah[mt][3]);
                    ldsm4(slab + OFF_AL + ea, al[mt][0], al[mt][1], al[mt][2], al[mt][3]);
                }
                #pragma unroll
                for (int p = 0; p < NPAIR2; p++) {
                    uint32_t eb = (uint32_t)((rowB2_base + p * 16) * ST + ks * 16 + kB_off) * 2;
                    uint32_t bh0, bh1, bh2, bh3, bl0, bl1, bl2, bl3;
                    ldsm4(b2base + eb, bh0, bh1, bh2, bh3);
                    ldsm4(b2base + (uint32_t)(N2 * ST * 2) + eb, bl0, bl1, bl2, bl3);
                    #pragma unroll
                    for (int mt = 0; mt < 2; mt++) {
                        float* c0 = acc2[mt][2 * p];
                        float* c1 = acc2[mt][2 * p + 1];
                        mma_bf16(c0, ah[mt], bh0, bh1);
                        mma_bf16(c0, ah[mt], bl0, bl1);
                        mma_bf16(c0, al[mt], bh0, bh1);
                        mma_bf16(c1, ah[mt], bh2, bh3);
                        mma_bf16(c1, ah[mt], bl2, bl3);
                        mma_bf16(c1, al[mt], bh2, bh3);
                    }
                }
            }
            __syncthreads();

            if (kb + 1 < 4) {
                loadB2(Bh, Bl, kb + 1);
            } else if (THREE && ph == 0) {
                loadB2(B3h, B3l, 0);     // preload next phase's first chunk
            }
        }

        #pragma unroll
        for (int mt = 0; mt < 2; mt++) {
            #pragma unroll
            for (int half = 0; half < 2; half++) {
                int r = blockRow + m0 + mt * 16 + g + half * 8;
                if (r >= M) continue;
                #pragma unroll
                for (int nt = 0; nt < NT2; nt++) {
                    int cc = n0b + nt * 8 + 2 * t;
                    float v0 = silu_f(acc2[mt][nt][half * 2 + 0]) * os2;
                    float v1 = silu_f(acc2[mt][nt][half * 2 + 1]) * os2;
                    ((__half2*)outp)[(size_t)r * (N2 / 2) + (cc >> 1)] =
                        __floats2half2_rn(v0, v1);
                }
            }
        }
        if (THREE && ph == 0) __syncthreads();
    }
}

// ---------------- triplet (FFMA, fp16 T pre-scaled by INV_SQRT_NB) ----------------
__global__ void __launch_bounds__(256)
triplet_kernel(const __half* __restrict__ T, const float* __restrict__ cbf,
               const int* __restrict__ idx_s, const int* __restrict__ basis,
               const float* __restrict__ Wc,
               __nv_bfloat16* __restrict__ Xh, __nv_bfloat16* __restrict__ Xl, int E)
{
    __shared__ float cb[8][128];
    const int warp = threadIdx.x >> 5;
    const int lane = threadIdx.x & 31;

    float w0[16], w1[16];
    #pragma unroll
    for (int c = 0; c < 16; c++) {
        w0[c] = Wc[c * 64 + 2 * lane];
        w1[c] = Wc[c * 64 + 2 * lane + 1];
    }

    const __half2* T2 = (const __half2*)T;
    const int gw = blockIdx.x * 8 + warp;
    const int nwarps = gridDim.x * 8;

    for (int e = gw; e < E; e += nwarps) {
        int s = idx_s[e];
        int b1v = 0;
        if (lane < 8) b1v = basis[s * 8 + lane];

        float4 v = *(const float4*)(cbf + (size_t)e * 128 + lane * 4);
        *(float4*)(&cb[warp][lane * 4]) = v;
        __syncwarp();

        int bidx[8];
        #pragma unroll
        for (int nb = 0; nb < 8; nb++)
            bidx[nb] = __shfl_sync(0xffffffffu, b1v, nb);

        __half2 tv[8];
        #pragma unroll
        for (int nb = 0; nb < 8; nb++)
            tv[nb] = T2[(size_t)bidx[nb] * 32 + lane];

        float acc0 = 0.f, acc1 = 0.f;
        #pragma unroll
        for (int nb = 0; nb < 8; nb++) {
            float d0 = 0.f, d1 = 0.f;
            #pragma unroll
            for (int c = 0; c < 16; c++) {
                float a = cb[warp][nb * 16 + c];
                d0 = fmaf(a, w0[c], d0);
                d1 = fmaf(a, w1[c], d1);
            }
            float2 tt = __half22float2(tv[nb]);
            acc0 = fmaf(tt.x, d0, acc0);
            acc1 = fmaf(tt.y, d1, acc1);
        }
        uint32_t H, L;
        split_pack(make_float2(acc0, acc1), H, L);
        ((uint32_t*)Xh)[(size_t)e * 32 + lane] = H;
        ((uint32_t*)Xl)[(size_t)e * 32 + lane] = L;
        __syncwarp();
    }
}

// ---------------- final elementwise: out = (XST + Z[swap]) * c ----------------
__global__ void __launch_bounds__(256)
final_ew(const __half* __restrict__ XST, const __half* __restrict__ Z,
         const int* __restrict__ swp, float* __restrict__ out, int E)
{
    size_t total = (size_t)E * 16;
    size_t stride = (size_t)gridDim.x * blockDim.x;
    for (size_t i = (size_t)blockIdx.x * blockDim.x + threadIdx.x; i < total; i += stride) {
        size_t e = i >> 4;
        int    q = (int)(i & 15);
        int    s = swp[e];
        uint4 a = ((const uint4*)XST)[i];
        uint4 b = ((const uint4*)Z)[(size_t)s * 16 + q];
        const __half2* ah = (const __half2*)&a;
        const __half2* bh = (const __half2*)&b;
        float4 o0, o1;
        float2 r0 = __half22float2(ah[0]), z0 = __half22float2(bh[0]);
        float2 r1 = __half22float2(ah[1]), z1 = __half22float2(bh[1]);
        float2 r2 = __half22float2(ah[2]), z2 = __half22float2(bh[2]);
        float2 r3 = __half22float2(ah[3]), z3 = __half22float2(bh[3]);
        o0.x = (r0.x + z0.x) * INV_SQRT_2; o0.y = (r0.y + z0.y) * INV_SQRT_2;
        o0.z = (r1.x + z1.x) * INV_SQRT_2; o0.w = (r1.y + z1.y) * INV_SQRT_2;
        o1.x = (r2.x + z2.x) * INV_SQRT_2; o1.y = (r2.y + z2.y) * INV_SQRT_2;
        o1.z = (r3.x + z3.x) * INV_SQRT_2; o1.w = (r3.y + z3.y) * INV_SQRT_2;
        ((float4*)out)[e * 32 + q * 2]     = o0;
        ((float4*)out)[e * 32 + q * 2 + 1] = o1;
    }
}

extern "C" void kernel_launch(void* const* d_in, const int* in_sizes, int n_in,
                              void* d_out, int out_size)
{
    const float* m_st     = (const float*)d_in[0];
    const float* rbf      = (const float*)d_in[1];
    const float* cbf      = (const float*)d_in[2];
    const int*   idx_s    = (const int*)d_in[3];
    const int*   idx_swap = (const int*)d_in[4];
    const int*   basis    = (const int*)d_in[5];
    const float* W_m_rbf  = (const float*)d_in[6];
    const float* W_rbf    = (const float*)d_in[7];
    const float* W_m_cbf  = (const float*)d_in[8];
    const float* W_cbf    = (const float*)d_in[9];
    const float* W_dir    = (const float*)d_in[10];
    const float* W_st     = (const float*)d_in[11];
    const float* W_ts     = (const float*)d_in[12];
    float* out = (float*)d_out;

    const int E = in_sizes[0] / DEDGE;

    __half *pT, *pZ, *pXST;
    __nv_bfloat16 *pmh, *pml, *pXh, *pXl;
    __nv_bfloat16 *wmrh, *wmrl, *wmch, *wmcl, *wdh, *wdl, *wsth, *wstl, *wtsh, *wtsl;
    cudaGetSymbolAddress((void**)&pT,   g_T);
    cudaGetSymbolAddress((void**)&pZ,   g_Z);
    cudaGetSymbolAddress((void**)&pXST, g_XST);
    cudaGetSymbolAddress((void**)&pmh,  g_msth);  cudaGetSymbolAddress((void**)&pml, g_mstl);
    cudaGetSymbolAddress((void**)&pXh,  g_Xh);    cudaGetSymbolAddress((void**)&pXl, g_Xl);
    cudaGetSymbolAddress((void**)&wmrh, g_Wmrh);  cudaGetSymbolAddress((void**)&wmrl, g_Wmrl);
    cudaGetSymbolAddress((void**)&wmch, g_Wmch);  cudaGetSymbolAddress((void**)&wmcl, g_Wmcl);
    cudaGetSymbolAddress((void**)&wdh,  g_Wdh);   cudaGetSymbolAddress((void**)&wdl, g_Wdl);
    cudaGetSymbolAddress((void**)&wsth, g_Wsth);  cudaGetSymbolAddress((void**)&wstl, g_Wstl);
    cudaGetSymbolAddress((void**)&wtsh, g_Wtsh);  cudaGetSymbolAddress((void**)&wtsl, g_Wtsl);

    const int gB = (E + 127) / 128;

    const int smem_f12 = 81920 + 2 * 64  * 40 * 2 + 8192;  // 100352
    const int smem_f45 = 81920 + 2 * 128 * 40 * 2;         // 102400

    cudaFuncSetAttribute(gemm_chain<128, 64, true, false>,
                         cudaFuncAttributeMaxDynamicSharedMemorySize, smem_f12);
    cudaFuncSetAttribute(gemm_chain<64, 128, false, true>,
                         cudaFuncAttributeMaxDynamicSharedMemorySize, smem_f45);

    // launch 0: split m_st
    split_rows<<<(E * 64 + 255) / 256, 256>>>(m_st, pmh, pml, E * 64);
    // launch 1: split all 5 weights
    {
        dim3 grid(64, 5);
        split_w_all<<<grid, 256>>>(
            W_m_rbf, wmrh, wmrl,
            W_m_cbf, wmch, wmcl,
            W_dir,   wdh,  wdl,
            W_st,    wsth, wstl,
            W_ts,    wtsh, wtsl);
    }
    // launch 2 (F12): M1 = silu(m_st@W_m_rbf) * (rbf@W_rbf) -> T(fp16, pre-scaled) = silu(M1@W_m_cbf)*INV_SQRT_NB
    gemm_chain<128, 64, true, false><<<gB, 256, smem_f12>>>(
        pmh, pml, wmrh, wmrl, rbf, W_rbf, wmch, wmcl, pT,
        nullptr, nullptr, nullptr, INV_SQRT_NB, E);
    // launch 3: triplet -> X bf16 hi/lo
    triplet_kernel<<<2048, 256>>>(pT, cbf, idx_s, basis, W_cbf, pXh, pXl, E);
    // launch 4 (F45, 3-phase): Y = silu(X@W_dir) (smem) -> Z(fp16)=silu(Y@W_ts), XST(fp16)=silu(Y@W_st)
    gemm_chain<64, 128, false, true><<<gB, 256, smem_f45>>>(
        pXh, pXl, wdh, wdl, nullptr, nullptr, wtsh, wtsl, pZ,
        wsth, wstl, pXST, 1.0f, E);
    // launch 5: out = (XST + Z[idx_swap]) * INV_SQRT_2
    final_ew<<<4096, 256>>>(pXST, pZ, idx_swap, out, E);
}

// round 13
// speedup vs baseline: 1.6156x; 1.1397x over previous
#include <cuda_runtime.h>
#include <cuda_fp16.h>
#include <cstdint>
#include <math.h>

#define EMAX   250000
#define DEDGE  128
#define DTRI   64

// fp16 intermediates
static __device__ __align__(16) __half g_T  [EMAX * DTRI];
static __device__ __align__(16) __half g_Z  [EMAX * DEDGE];
static __device__ __align__(16) __half g_XST[EMAX * DEDGE];
static __device__ __align__(16) __half g_mst[EMAX * DEDGE];
static __device__ __align__(16) __half g_X  [EMAX * DTRI];
// fp16 hi/lo transposed weights [N][K] (exact to ~2^-22)
static __device__ __align__(16) __half g_Wmrh [128 * 128], g_Wmrl [128 * 128];
static __device__ __align__(16) __half g_Wmch [64 * 128],  g_Wmcl [64 * 128];
static __device__ __align__(16) __half g_Wdh  [128 * 64],  g_Wdl  [128 * 64];
static __device__ __align__(16) __half g_Wsth [128 * 128], g_Wstl [128 * 128];
static __device__ __align__(16) __half g_Wtsh [128 * 128], g_Wtsl [128 * 128];

#define INV_SQRT_2  0.70710678118654752440f
#define INV_SQRT_NB 0.35355339059327376220f

__device__ __forceinline__ float silu_f(float x) {
    return x / (1.0f + __expf(-x));
}
__device__ __forceinline__ uint32_t smem_u32(const void* p) {
    uint32_t a;
    asm("{ .reg .u64 t; cvta.to.shared.u64 t, %1; cvt.u32.u64 %0, t; }" : "=r"(a) : "l"(p));
    return a;
}
__device__ __forceinline__ void cp_async16(uint32_t dst, const void* src, bool v) {
    int sz = v ? 16 : 0;
    asm volatile("cp.async.cg.shared.global [%0], [%1], 16, %2;"
                 :: "r"(dst), "l"(src), "r"(sz));
}
#define CP_COMMIT() asm volatile("cp.async.commit_group;" ::: "memory")
template<int n> __device__ __forceinline__ void cp_wait() {
    asm volatile("cp.async.wait_group %0;" :: "n"(n) : "memory");
}
__device__ __forceinline__ void ldsm4(uint32_t addr, uint32_t& r0, uint32_t& r1,
                                      uint32_t& r2, uint32_t& r3) {
    asm volatile("ldmatrix.sync.aligned.m8n8.x4.shared.b16 {%0,%1,%2,%3}, [%4];"
                 : "=r"(r0), "=r"(r1), "=r"(r2), "=r"(r3) : "r"(addr));
}
__device__ __forceinline__ void mma_fp16(float* c, const uint32_t* a,
                                         uint32_t b0, uint32_t b1) {
    asm volatile(
        "mma.sync.aligned.m16n8k16.row.col.f32.f16.f16.f32 "
        "{%0,%1,%2,%3}, {%4,%5,%6,%7}, {%8,%9}, {%0,%1,%2,%3};"
        : "+f"(c[0]), "+f"(c[1]), "+f"(c[2]), "+f"(c[3])
        : "r"(a[0]), "r"(a[1]), "r"(a[2]), "r"(a[3]), "r"(b0), "r"(b1));
}
__device__ __forceinline__ uint32_t packh2(float x, float y) {
    __half2 p = __floats2half2_rn(x, y);
    return *(uint32_t*)&p;
}

// ---------------- setup kernels ----------------
// m_st fp32 -> fp16 single
__global__ void conv_rows(const float* __restrict__ src, __half* __restrict__ dst, int n2)
{
    int i = blockIdx.x * blockDim.x + threadIdx.x;
    if (i >= n2) return;
    float2 v = ((const float2*)src)[i];
    ((uint32_t*)dst)[i] = packh2(v.x, v.y);
}

// W[K][N] fp32 -> Wt[N][K] fp16 hi/lo
__global__ void split_w_all(
    const float* __restrict__ s0, __half* __restrict__ d0h, __half* __restrict__ d0l,
    const float* __restrict__ s1, __half* __restrict__ d1h, __half* __restrict__ d1l,
    const float* __restrict__ s2, __half* __restrict__ d2h, __half* __restrict__ d2l,
    const float* __restrict__ s3, __half* __restrict__ d3h, __half* __restrict__ d3l,
    const float* __restrict__ s4, __half* __restrict__ d4h, __half* __restrict__ d4l)
{
    int i = blockIdx.x * blockDim.x + threadIdx.x;
    int w = blockIdx.y;
    const float* src; __half *dh, *dl; int K, N;
    switch (w) {
        case 0: src = s0; dh = d0h; dl = d0l; K = 128; N = 128; break;
        case 1: src = s1; dh = d1h; dl = d1l; K = 128; N = 64;  break;
        case 2: src = s2; dh = d2h; dl = d2l; K = 64;  N = 128; break;
        case 3: src = s3; dh = d3h; dl = d3l; K = 128; N = 128; break;
        default: src = s4; dh = d4h; dl = d4l; K = 128; N = 128; break;
    }
    if (i >= K * N) return;
    int k = i / N, n = i % N;
    float v = src[i];
    __half h = __float2half(v);
    __half l = __float2half(v - __half2float(h));
    dh[n * K + k] = h;
    dl[n * K + k] = l;
}

// ---------------- chained GEMM (2 or 3 phases), fp16 A-single x fp16 B-split2 ----------------
// Phase1: P = silu(A @ B1^T) [* R(rbf@Wrbf fp32 in epilogue)] -> smem slabs (fp16)
// Phase2: out2(fp16) = os2 * silu(P @ B2^T)
// Phase3 (if THREE): out3(fp16) = os2 * silu(P @ B3^T)
template<int K1, int N2, bool HAS_R, bool THREE>
__global__ void __launch_bounds__(256, 2)
gemm_chain(const __half* __restrict__ Ah,
           const __half* __restrict__ B1h, const __half* __restrict__ B1l,
           const float* __restrict__ rbf_g, const float* __restrict__ Wrbf_g,
           const __half* __restrict__ B2h, const __half* __restrict__ B2l,
           __half* __restrict__ out2,
           const __half* __restrict__ B3h, const __half* __restrict__ B3l,
           __half* __restrict__ out3, float os2, int M)
{
    constexpr int N1  = 128;
    constexpr int ST  = 40;                                 // halfs per row
    constexpr int NCH1 = (K1 + 31) / 32;
    constexpr uint32_t OFF_BH = 128 * ST * 2;               // 10240 (A region size)
    constexpr uint32_t OFF_BL = OFF_BH + N1 * ST * 2;       // 20480
    constexpr uint32_t SSZ    = OFF_BH + 2 * N1 * ST * 2;   // 30720
    constexpr uint32_t SLAB   = 128 * ST * 2;               // 10240 per k-chunk (fp16 single)
    constexpr uint32_t B2OFF  = 2 * SSZ;                    // 61440
    constexpr uint32_t WOFF   = B2OFF + 2u * N2 * ST * 2;
    constexpr int NT2   = N2 / 16;
    constexpr int NPAIR2 = NT2 / 2;

    extern __shared__ __align__(16) char smu[];
    const uint32_t sbase = smem_u32(smu);

    const int tid  = threadIdx.x;
    const int warp = tid >> 5, lane = tid & 31;
    const int g = lane >> 2, t = lane & 3;
    const int warpM = warp & 3, warpN = warp >> 2;
    const int m0 = warpM * 32;
    const int n0 = warpN * 64;
    const int n0b = warpN * (N2 / 2);
    const int blockRow = blockIdx.x * 128;

    const int lr  = lane & 7;
    const int rowA_base = m0 + lr + ((lane >> 3) & 1) * 8;
    const int kA_off    = (lane >> 4) * 8;
    const int rowB_base = n0 + lr + (lane >> 4) * 8;
    const int rowB2_base = n0b + lr + (lane >> 4) * 8;
    const int kB_off    = ((lane >> 3) & 1) * 8;

    const uint32_t b2base = sbase + B2OFF;

    // phase-2/3 B chunk loader (commits one group)
    auto loadB2 = [&](const __half* Bh, const __half* Bl, int kb) {
        #pragma unroll
        for (int j = 0; j < (N2 * 4) / 256; j++) {
            int gg = tid + j * 256;
            int n = gg >> 2, q = gg & 3;
            size_t so = (size_t)n * 128 + kb * 32 + q * 8;
            uint32_t d = b2base + (uint32_t)(n * ST + q * 8) * 2;
            cp_async16(d, Bh + so, true);
            cp_async16(d + (uint32_t)(N2 * ST * 2), Bl + so, true);
        }
        CP_COMMIT();
    };

    // ======== phase 1 ========
    {
        float acc[2][8][4];
        #pragma unroll
        for (int mt = 0; mt < 2; mt++)
            #pragma unroll
            for (int nt = 0; nt < 8; nt++)
                #pragma unroll
                for (int j = 0; j < 4; j++) acc[mt][nt][j] = 0.0f;

        auto load_chunk = [&](int kb, int stage) {
            const int k0 = kb * 32;
            const uint32_t sb = sbase + (uint32_t)stage * SSZ;
            // A single fp16: 512 granules
            #pragma unroll
            for (int j = 0; j < 2; j++) {
                int gg = tid + j * 256;
                int row = gg >> 2, q = gg & 3;
                bool v = (blockRow + row < M) && (k0 + q * 8 < K1);
                size_t so = (size_t)(blockRow + row) * K1 + k0 + q * 8;
                uint32_t d = sb + (uint32_t)(row * ST + q * 8) * 2;
                cp_async16(d, v ? (Ah + so) : Ah, v);
            }
            // B hi/lo
            #pragma unroll
            for (int j = 0; j < 2; j++) {
                int gg = tid + j * 256;
                int n = gg >> 2, q = gg & 3;
                bool v = (k0 + q * 8 < K1);
                size_t so = (size_t)n * K1 + k0 + q * 8;
                uint32_t d = sb + OFF_BH + (uint32_t)(n * ST + q * 8) * 2;
                cp_async16(d, v ? (B1h + so) : B1h, v);
                cp_async16(d + (uint32_t)(N1 * ST * 2), v ? (B1l + so) : B1l, v);
            }
            CP_COMMIT();
        };

        if (HAS_R) {
            #pragma unroll
            for (int j = 0; j < 2; j++) {
                int q = tid + j * 256;
                cp_async16(sbase + WOFF + (uint32_t)q * 16, Wrbf_g + q * 4, true);
            }
        }
        load_chunk(0, 0);
        for (int kb = 0; kb < NCH1; kb++) {
            if (kb + 1 < NCH1) { load_chunk(kb + 1, (kb + 1) & 1); cp_wait<1>(); }
            else               { cp_wait<0>(); }
            __syncthreads();

            const uint32_t sb = sbase + (uint32_t)(kb & 1) * SSZ;
            #pragma unroll
            for (int ks = 0; ks < 2; ks++) {
                uint32_t ah[2][4];
                #pragma unroll
                for (int mt = 0; mt < 2; mt++) {
                    uint32_t ea = (uint32_t)((rowA_base + mt * 16) * ST + ks * 16 + kA_off) * 2;
                    ldsm4(sb + ea, ah[mt][0], ah[mt][1], ah[mt][2], ah[mt][3]);
                }
                #pragma unroll
                for (int p = 0; p < 4; p++) {
                    uint32_t eb = (uint32_t)((rowB_base + p * 16) * ST + ks * 16 + kB_off) * 2;
                    uint32_t bh0, bh1, bh2, bh3, bl0, bl1, bl2, bl3;
                    ldsm4(sb + OFF_BH + eb, bh0, bh1, bh2, bh3);
                    ldsm4(sb + OFF_BL + eb, bl0, bl1, bl2, bl3);
                    #pragma unroll
                    for (int mt = 0; mt < 2; mt++) {
                        float* c0 = acc[mt][2 * p];
                        float* c1 = acc[mt][2 * p + 1];
                        mma_fp16(c0, ah[mt], bh0, bh1);
                        mma_fp16(c0, ah[mt], bl0, bl1);
                        mma_fp16(c1, ah[mt], bh2, bh3);
                        mma_fp16(c1, ah[mt], bl2, bl3);
                    }
                }
            }
            __syncthreads();
        }

        // preload phase-2 first B chunk (B buffer idle during epilogue 1)
        loadB2(B2h, B2l, 0);

        // epilogue 1: silu [* R], fp16 -> slabs
        const float2* Wsm2 = (const float2*)(smu + WOFF);
        #pragma unroll
        for (int mt = 0; mt < 2; mt++) {
            int row0 = m0 + mt * 16 + g;
            int row1 = row0 + 8;
            int gr0 = blockRow + row0, gr1 = blockRow + row1;
            float rb0[16], rb1[16];
            if (HAS_R) {
                #pragma unroll
                for (int q = 0; q < 4; q++) {
                    float4 v0 = make_float4(0.f, 0.f, 0.f, 0.f);
                    float4 v1 = make_float4(0.f, 0.f, 0.f, 0.f);
                    if (gr0 < M) v0 = *(const float4*)(rbf_g + (size_t)gr0 * 16 + q * 4);
                    if (gr1 < M) v1 = *(const float4*)(rbf_g + (size_t)gr1 * 16 + q * 4);
                    rb0[q * 4 + 0] = v0.x; rb0[q * 4 + 1] = v0.y;
                    rb0[q * 4 + 2] = v0.z; rb0[q * 4 + 3] = v0.w;
                    rb1[q * 4 + 0] = v1.x; rb1[q * 4 + 1] = v1.y;
                    rb1[q * 4 + 2] = v1.z; rb1[q * 4 + 3] = v1.w;
                }
            }
            #pragma unroll
            for (int nt = 0; nt < 8; nt++) {
                int cc = n0 + nt * 8 + 2 * t;
                float r00 = 1.f, r01 = 1.f, r10 = 1.f, r11 = 1.f;
                if (HAS_R) {
                    r00 = r01 = r10 = r11 = 0.f;
                    #pragma unroll
                    for (int k = 0; k < 16; k++) {
                        float2 w = Wsm2[k * 64 + (cc >> 1)];
                        r00 = fmaf(rb0[k], w.x, r00); r01 = fmaf(rb0[k], w.y, r01);
                        r10 = fmaf(rb1[k], w.x, r10); r11 = fmaf(rb1[k], w.y, r11);
                    }
                }
                float v00 = silu_f(acc[mt][nt][0]) * r00;
                float v01 = silu_f(acc[mt][nt][1]) * r01;
                float v10 = silu_f(acc[mt][nt][2]) * r10;
                float v11 = silu_f(acc[mt][nt][3]) * r11;
                if (gr0 >= M) { v00 = 0.f; v01 = 0.f; }
                if (gr1 >= M) { v10 = 0.f; v11 = 0.f; }
                uint32_t H0 = packh2(v00, v01);
                uint32_t H1 = packh2(v10, v11);
                uint32_t chunk = (uint32_t)(cc >> 5);
                uint32_t off0 = (uint32_t)(row0 * ST + (cc & 31)) * 2;
                uint32_t off1 = (uint32_t)(row1 * ST + (cc & 31)) * 2;
                *(uint32_t*)(smu + chunk * SLAB + off0) = H0;
                *(uint32_t*)(smu + chunk * SLAB + off1) = H1;
            }
        }
        __syncthreads();
    }

    // ======== phase 2 (+3): silu(P @ B^T) * os2 -> fp16, K = 128 ========
    #pragma unroll
    for (int ph = 0; ph < (THREE ? 2 : 1); ph++) {
        const __half* Bh = (ph == 0) ? B2h : B3h;
        const __half* Bl = (ph == 0) ? B2l : B3l;
        __half* outp = (ph == 0) ? out2 : out3;

        float acc2[2][NT2][4];
        #pragma unroll
        for (int mt = 0; mt < 2; mt++)
            #pragma unroll
            for (int nt = 0; nt < NT2; nt++)
                #pragma unroll
                for (int j = 0; j < 4; j++) acc2[mt][nt][j] = 0.0f;

        for (int kb = 0; kb < 4; kb++) {
            cp_wait<0>();
            __syncthreads();

            const uint32_t slab = sbase + (uint32_t)kb * SLAB;
            #pragma unroll
            for (int ks = 0; ks < 2; ks++) {
                uint32_t ah[2][4];
                #pragma unroll
                for (int mt = 0; mt < 2; mt++) {
                    uint32_t ea = (uint32_t)((rowA_base + mt * 16) * ST + ks * 16 + kA_off) * 2;
                    ldsm4(slab + ea, ah[mt][0], ah[mt][1], ah[mt][2], ah[mt][3]);
                }
                #pragma unroll
                for (int p = 0; p < NPAIR2; p++) {
                    uint32_t eb = (uint32_t)((rowB2_base + p * 16) * ST + ks * 16 + kB_off) * 2;
                    uint32_t bh0, bh1, bh2, bh3, bl0, bl1, bl2, bl3;
                    ldsm4(b2base + eb, bh0, bh1, bh2, bh3);
                    ldsm4(b2base + (uint32_t)(N2 * ST * 2) + eb, bl0, bl1, bl2, bl3);
                    #pragma unroll
                    for (int mt = 0; mt < 2; mt++) {
                        float* c0 = acc2[mt][2 * p];
                        float* c1 = acc2[mt][2 * p + 1];
                        mma_fp16(c0, ah[mt], bh0, bh1);
                        mma_fp16(c0, ah[mt], bl0, bl1);
                        mma_fp16(c1, ah[mt], bh2, bh3);
                        mma_fp16(c1, ah[mt], bl2, bl3);
                    }
                }
            }
            __syncthreads();

            if (kb + 1 < 4) {
                loadB2(Bh, Bl, kb + 1);
            } else if (THREE && ph == 0) {
                loadB2(B3h, B3l, 0);
            }
        }

        #pragma unroll
        for (int mt = 0; mt < 2; mt++) {
            #pragma unroll
            for (int half = 0; half < 2; half++) {
                int r = blockRow + m0 + mt * 16 + g + half * 8;
                if (r >= M) continue;
                #pragma unroll
                for (int nt = 0; nt < NT2; nt++) {
                    int cc = n0b + nt * 8 + 2 * t;
                    float v0 = silu_f(acc2[mt][nt][half * 2 + 0]) * os2;
                    float v1 = silu_f(acc2[mt][nt][half * 2 + 1]) * os2;
                    ((uint32_t*)outp)[(size_t)r * (N2 / 2) + (cc >> 1)] = packh2(v0, v1);
                }
            }
        }
        if (THREE && ph == 0) __syncthreads();
    }
}

// ---------------- triplet (FFMA, fp16 T pre-scaled, fp16 X out) ----------------
__global__ void __launch_bounds__(256)
triplet_kernel(const __half* __restrict__ T, const float* __restrict__ cbf,
               const int* __restrict__ idx_s, const int* __restrict__ basis,
               const float* __restrict__ Wc,
               __half* __restrict__ X, int E)
{
    __shared__ float cb[8][128];
    const int warp = threadIdx.x >> 5;
    const int lane = threadIdx.x & 31;

    float w0[16], w1[16];
    #pragma unroll
    for (int c = 0; c < 16; c++) {
        w0[c] = Wc[c * 64 + 2 * lane];
        w1[c] = Wc[c * 64 + 2 * lane + 1];
    }

    const __half2* T2 = (const __half2*)T;
    const int gw = blockIdx.x * 8 + warp;
    const int nwarps = gridDim.x * 8;

    for (int e = gw; e < E; e += nwarps) {
        int s = idx_s[e];
        int b1v = 0;
        if (lane < 8) b1v = basis[s * 8 + lane];

        float4 v = *(const float4*)(cbf + (size_t)e * 128 + lane * 4);
        *(float4*)(&cb[warp][lane * 4]) = v;
        __syncwarp();

        int bidx[8];
        #pragma unroll
        for (int nb = 0; nb < 8; nb++)
            bidx[nb] = __shfl_sync(0xffffffffu, b1v, nb);

        __half2 tv[8];
        #pragma unroll
        for (int nb = 0; nb < 8; nb++)
            tv[nb] = T2[(size_t)bidx[nb] * 32 + lane];

        float acc0 = 0.f, acc1 = 0.f;
        #pragma unroll
        for (int nb = 0; nb < 8; nb++) {
            float d0 = 0.f, d1 = 0.f;
            #pragma unroll
            for (int c = 0; c < 16; c++) {
                float a = cb[warp][nb * 16 + c];
                d0 = fmaf(a, w0[c], d0);
                d1 = fmaf(a, w1[c], d1);
            }
            float2 tt = __half22float2(tv[nb]);
            acc0 = fmaf(tt.x, d0, acc0);
            acc1 = fmaf(tt.y, d1, acc1);
        }
        ((uint32_t*)X)[(size_t)e * 32 + lane] = packh2(acc0, acc1);
        __syncwarp();
    }
}

// ---------------- final elementwise: out = (XST + Z[swap]) * c ----------------
__global__ void __launch_bounds__(256)
final_ew(const __half* __restrict__ XST, const __half* __restrict__ Z,
         const int* __restrict__ swp, float* __restrict__ out, int E)
{
    size_t total = (size_t)E * 16;
    size_t stride = (size_t)gridDim.x * blockDim.x;
    for (size_t i = (size_t)blockIdx.x * blockDim.x + threadIdx.x; i < total; i += stride) {
        size_t e = i >> 4;
        int    q = (int)(i & 15);
        int    s = swp[e];
        uint4 a = ((const uint4*)XST)[i];
        uint4 b = ((const uint4*)Z)[(size_t)s * 16 + q];
        const __half2* ah = (const __half2*)&a;
        const __half2* bh = (const __half2*)&b;
        float4 o0, o1;
        float2 r0 = __half22float2(ah[0]), z0 = __half22float2(bh[0]);
        float2 r1 = __half22float2(ah[1]), z1 = __half22float2(bh[1]);
        float2 r2 = __half22float2(ah[2]), z2 = __half22float2(bh[2]);
        float2 r3 = __half22float2(ah[3]), z3 = __half22float2(bh[3]);
        o0.x = (r0.x + z0.x) * INV_SQRT_2; o0.y = (r0.y + z0.y) * INV_SQRT_2;
        o0.z = (r1.x + z1.x) * INV_SQRT_2; o0.w = (r1.y + z1.y) * INV_SQRT_2;
        o1.x = (r2.x + z2.x) * INV_SQRT_2; o1.y = (r2.y + z2.y) * INV_SQRT_2;
        o1.z = (r3.x + z3.x) * INV_SQRT_2; o1.w = (r3.y + z3.y) * INV_SQRT_2;
        ((float4*)out)[e * 32 + q * 2]     = o0;
        ((float4*)out)[e * 32 + q * 2 + 1] = o1;
    }
}

extern "C" void kernel_launch(void* const* d_in, const int* in_sizes, int n_in,
                              void* d_out, int out_size)
{
    const float* m_st     = (const float*)d_in[0];
    const float* rbf      = (const float*)d_in[1];
    const float* cbf      = (const float*)d_in[2];
    const int*   idx_s    = (const int*)d_in[3];
    const int*   idx_swap = (const int*)d_in[4];
    const int*   basis    = (const int*)d_in[5];
    const float* W_m_rbf  = (const float*)d_in[6];
    const float* W_rbf    = (const float*)d_in[7];
    const float* W_m_cbf  = (const float*)d_in[8];
    const float* W_cbf    = (const float*)d_in[9];
    const float* W_dir    = (const float*)d_in[10];
    const float* W_st     = (const float*)d_in[11];
    const float* W_ts     = (const float*)d_in[12];
    float* out = (float*)d_out;

    const int E = in_sizes[0] / DEDGE;

    __half *pT, *pZ, *pXST, *pm, *pX;
    __half *wmrh, *wmrl, *wmch, *wmcl, *wdh, *wdl, *wsth, *wstl, *wtsh, *wtsl;
    cudaGetSymbolAddress((void**)&pT,   g_T);
    cudaGetSymbolAddress((void**)&pZ,   g_Z);
    cudaGetSymbolAddress((void**)&pXST, g_XST);
    cudaGetSymbolAddress((void**)&pm,   g_mst);
    cudaGetSymbolAddress((void**)&pX,   g_X);
    cudaGetSymbolAddress((void**)&wmrh, g_Wmrh);  cudaGetSymbolAddress((void**)&wmrl, g_Wmrl);
    cudaGetSymbolAddress((void**)&wmch, g_Wmch);  cudaGetSymbolAddress((void**)&wmcl, g_Wmcl);
    cudaGetSymbolAddress((void**)&wdh,  g_Wdh);   cudaGetSymbolAddress((void**)&wdl, g_Wdl);
    cudaGetSymbolAddress((void**)&wsth, g_Wsth);  cudaGetSymbolAddress((void**)&wstl, g_Wstl);
    cudaGetSymbolAddress((void**)&wtsh, g_Wtsh);  cudaGetSymbolAddress((void**)&wtsl, g_Wtsl);

    const int gB = (E + 127) / 128;

    // smem: 2 stages (30720 each) + B2 buffer + optional Wrbf
    const int smem_f12 = 61440 + 2 * 64  * 40 * 2 + 8192;  // 79872
    const int smem_f45 = 61440 + 2 * 128 * 40 * 2;         // 81920

    cudaFuncSetAttribute(gemm_chain<128, 64, true, false>,
                         cudaFuncAttributeMaxDynamicSharedMemorySize, smem_f12);
    cudaFuncSetAttribute(gemm_chain<64, 128, false, true>,
                         cudaFuncAttributeMaxDynamicSharedMemorySize, smem_f45);

    // launch 0: m_st -> fp16
    conv_rows<<<(E * 64 + 255) / 256, 256>>>(m_st, pm, E * 64);
    // launch 1: split all 5 weights (fp16 hi/lo, transposed)
    {
        dim3 grid(64, 5);
        split_w_all<<<grid, 256>>>(
            W_m_rbf, wmrh, wmrl,
            W_m_cbf, wmch, wmcl,
            W_dir,   wdh,  wdl,
            W_st,    wsth, wstl,
            W_ts,    wtsh, wtsl);
    }
    // launch 2 (F12): M1 = silu(m_st@W_m_rbf)*(rbf@W_rbf) -> T(fp16, pre-scaled)
    gemm_chain<128, 64, true, false><<<gB, 256, smem_f12>>>(
        pm, wmrh, wmrl, rbf, W_rbf, wmch, wmcl, pT,
        nullptr, nullptr, nullptr, INV_SQRT_NB, E);
    // launch 3: triplet -> X fp16
    triplet_kernel<<<2048, 256>>>(pT, cbf, idx_s, basis, W_cbf, pX, E);
    // launch 4 (F45, 3-phase): Y = silu(X@W_dir) -> Z(fp16)=silu(Y@W_ts), XST(fp16)=silu(Y@W_st)
    gemm_chain<64, 128, false, true><<<gB, 256, smem_f45>>>(
        pX, wdh, wdl, nullptr, nullptr, wtsh, wtsl, pZ,
        wsth, wstl, pXST, 1.0f, E);
    // launch 5: out = (XST + Z[idx_swap]) * INV_SQRT_2
    final_ew<<<4096, 256>>>(pXST, pZ, idx_swap, out, E);
}

// round 14
// speedup vs baseline: 1.6419x; 1.0163x over previous
#include <cuda_runtime.h>
#include <cuda_fp16.h>
#include <cstdint>
#include <math.h>

#define EMAX   250000
#define DEDGE  128
#define DTRI   64

// fp16 intermediates
static __device__ __align__(16) __half g_T  [EMAX * DTRI];
static __device__ __align__(16) __half g_Z  [EMAX * DEDGE];
static __device__ __align__(16) __half g_XST[EMAX * DEDGE];
static __device__ __align__(16) __half g_mst[EMAX * DEDGE];
static __device__ __align__(16) __half g_X  [EMAX * DTRI];
// fp16 hi/lo transposed weights [N][K] (exact to ~2^-22)
static __device__ __align__(16) __half g_Wmrh [128 * 128], g_Wmrl [128 * 128];
static __device__ __align__(16) __half g_Wmch [64 * 128],  g_Wmcl [64 * 128];
static __device__ __align__(16) __half g_Wdh  [128 * 64],  g_Wdl  [128 * 64];
static __device__ __align__(16) __half g_Wsth [128 * 128], g_Wstl [128 * 128];
static __device__ __align__(16) __half g_Wtsh [128 * 128], g_Wtsl [128 * 128];

#define INV_SQRT_2  0.70710678118654752440f
#define INV_SQRT_NB 0.35355339059327376220f

__device__ __forceinline__ float silu_f(float x) {
    return x / (1.0f + __expf(-x));
}
__device__ __forceinline__ uint32_t smem_u32(const void* p) {
    uint32_t a;
    asm("{ .reg .u64 t; cvta.to.shared.u64 t, %1; cvt.u32.u64 %0, t; }" : "=r"(a) : "l"(p));
    return a;
}
__device__ __forceinline__ void cp_async16(uint32_t dst, const void* src, bool v) {
    int sz = v ? 16 : 0;
    asm volatile("cp.async.cg.shared.global [%0], [%1], 16, %2;"
                 :: "r"(dst), "l"(src), "r"(sz));
}
#define CP_COMMIT() asm volatile("cp.async.commit_group;" ::: "memory")
template<int n> __device__ __forceinline__ void cp_wait() {
    asm volatile("cp.async.wait_group %0;" :: "n"(n) : "memory");
}
__device__ __forceinline__ void ldsm4(uint32_t addr, uint32_t& r0, uint32_t& r1,
                                      uint32_t& r2, uint32_t& r3) {
    asm volatile("ldmatrix.sync.aligned.m8n8.x4.shared.b16 {%0,%1,%2,%3}, [%4];"
                 : "=r"(r0), "=r"(r1), "=r"(r2), "=r"(r3) : "r"(addr));
}
__device__ __forceinline__ void mma_fp16(float* c, const uint32_t* a,
                                         uint32_t b0, uint32_t b1) {
    asm volatile(
        "mma.sync.aligned.m16n8k16.row.col.f32.f16.f16.f32 "
        "{%0,%1,%2,%3}, {%4,%5,%6,%7}, {%8,%9}, {%0,%1,%2,%3};"
        : "+f"(c[0]), "+f"(c[1]), "+f"(c[2]), "+f"(c[3])
        : "r"(a[0]), "r"(a[1]), "r"(a[2]), "r"(a[3]), "r"(b0), "r"(b1));
}
__device__ __forceinline__ uint32_t packh2(float x, float y) {
    __half2 p = __floats2half2_rn(x, y);
    return *(uint32_t*)&p;
}

// ---------------- setup kernels ----------------
__global__ void conv_rows(const float* __restrict__ src, __half* __restrict__ dst, int n2)
{
    int i = blockIdx.x * blockDim.x + threadIdx.x;
    if (i >= n2) return;
    float2 v = ((const float2*)src)[i];
    ((uint32_t*)dst)[i] = packh2(v.x, v.y);
}

__global__ void split_w_all(
    const float* __restrict__ s0, __half* __restrict__ d0h, __half* __restrict__ d0l,
    const float* __restrict__ s1, __half* __restrict__ d1h, __half* __restrict__ d1l,
    const float* __restrict__ s2, __half* __restrict__ d2h, __half* __restrict__ d2l,
    const float* __restrict__ s3, __half* __restrict__ d3h, __half* __restrict__ d3l,
    const float* __restrict__ s4, __half* __restrict__ d4h, __half* __restrict__ d4l)
{
    int i = blockIdx.x * blockDim.x + threadIdx.x;
    int w = blockIdx.y;
    const float* src; __half *dh, *dl; int K, N;
    switch (w) {
        case 0: src = s0; dh = d0h; dl = d0l; K = 128; N = 128; break;
        case 1: src = s1; dh = d1h; dl = d1l; K = 128; N = 64;  break;
        case 2: src = s2; dh = d2h; dl = d2l; K = 64;  N = 128; break;
        case 3: src = s3; dh = d3h; dl = d3l; K = 128; N = 128; break;
        default: src = s4; dh = d4h; dl = d4l; K = 128; N = 128; break;
    }
    if (i >= K * N) return;
    int k = i / N, n = i % N;
    float v = src[i];
    __half h = __float2half(v);
    __half l = __float2half(v - __half2float(h));
    dh[n * K + k] = h;
    dl[n * K + k] = l;
}

// ---------------- chained GEMM (2 or 3 phases), fp16 A-single x fp16 B-split2 ----------------
// Phase1: P = silu(A @ B1^T) [* R(rbf@Wrbf fp32 in epilogue)] -> smem slabs (fp16)
// Phase2: out2(fp16) = os2 * silu(P @ B2^T)
// Phase3 (if THREE): out3(fp16) = os2 * silu(P @ B3^T)
// Phases 2/3 use double-buffered B (2 buffers, one chunk ahead).
template<int K1, int N2, bool HAS_R, bool THREE>
__global__ void __launch_bounds__(256, 2)
gemm_chain(const __half* __restrict__ Ah,
           const __half* __restrict__ B1h, const __half* __restrict__ B1l,
           const float* __restrict__ rbf_g, const float* __restrict__ Wrbf_g,
           const __half* __restrict__ B2h, const __half* __restrict__ B2l,
           __half* __restrict__ out2,
           const __half* __restrict__ B3h, const __half* __restrict__ B3l,
           __half* __restrict__ out3, float os2, int M)
{
    constexpr int N1  = 128;
    constexpr int ST  = 40;                                 // halfs per row
    constexpr int NCH1 = (K1 + 31) / 32;
    constexpr uint32_t OFF_BH = 128 * ST * 2;               // 10240 (A region size)
    constexpr uint32_t OFF_BL = OFF_BH + N1 * ST * 2;       // 20480
    constexpr uint32_t SSZ    = OFF_BH + 2 * N1 * ST * 2;   // 30720
    constexpr uint32_t SLAB   = 128 * ST * 2;               // 10240 per k-chunk (fp16 single)
    constexpr uint32_t B2OFF  = 2 * SSZ;                    // 61440
    constexpr uint32_t BB     = 2u * N2 * ST * 2;           // one phase-2/3 B buffer
    constexpr uint32_t WOFF   = B2OFF + 2 * BB;
    constexpr int NT2   = N2 / 16;
    constexpr int NPAIR2 = NT2 / 2;

    extern __shared__ __align__(16) char smu[];
    const uint32_t sbase = smem_u32(smu);

    const int tid  = threadIdx.x;
    const int warp = tid >> 5, lane = tid & 31;
    const int g = lane >> 2, t = lane & 3;
    const int warpM = warp & 3, warpN = warp >> 2;
    const int m0 = warpM * 32;
    const int n0 = warpN * 64;
    const int n0b = warpN * (N2 / 2);
    const int blockRow = blockIdx.x * 128;

    const int lr  = lane & 7;
    const int rowA_base = m0 + lr + ((lane >> 3) & 1) * 8;
    const int kA_off    = (lane >> 4) * 8;
    const int rowB_base = n0 + lr + (lane >> 4) * 8;
    const int rowB2_base = n0b + lr + (lane >> 4) * 8;
    const int kB_off    = ((lane >> 3) & 1) * 8;

    // phase-2/3 B chunk loader into buffer buf (commits one group)
    auto loadB2 = [&](const __half* Bh, const __half* Bl, int kb, int buf) {
        const uint32_t bb = sbase + B2OFF + (uint32_t)buf * BB;
        #pragma unroll
        for (int j = 0; j < (N2 * 4) / 256; j++) {
            int gg = tid + j * 256;
            int n = gg >> 2, q = gg & 3;
            size_t so = (size_t)n * 128 + kb * 32 + q * 8;
            uint32_t d = bb + (uint32_t)(n * ST + q * 8) * 2;
            cp_async16(d, Bh + so, true);
            cp_async16(d + (uint32_t)(N2 * ST * 2), Bl + so, true);
        }
        CP_COMMIT();
    };

    // ======== phase 1 ========
    {
        float acc[2][8][4];
        #pragma unroll
        for (int mt = 0; mt < 2; mt++)
            #pragma unroll
            for (int nt = 0; nt < 8; nt++)
                #pragma unroll
                for (int j = 0; j < 4; j++) acc[mt][nt][j] = 0.0f;

        auto load_chunk = [&](int kb, int stage) {
            const int k0 = kb * 32;
            const uint32_t sb = sbase + (uint32_t)stage * SSZ;
            #pragma unroll
            for (int j = 0; j < 2; j++) {
                int gg = tid + j * 256;
                int row = gg >> 2, q = gg & 3;
                bool v = (blockRow + row < M) && (k0 + q * 8 < K1);
                size_t so = (size_t)(blockRow + row) * K1 + k0 + q * 8;
                uint32_t d = sb + (uint32_t)(row * ST + q * 8) * 2;
                cp_async16(d, v ? (Ah + so) : Ah, v);
            }
            #pragma unroll
            for (int j = 0; j < 2; j++) {
                int gg = tid + j * 256;
                int n = gg >> 2, q = gg & 3;
                bool v = (k0 + q * 8 < K1);
                size_t so = (size_t)n * K1 + k0 + q * 8;
                uint32_t d = sb + OFF_BH + (uint32_t)(n * ST + q * 8) * 2;
                cp_async16(d, v ? (B1h + so) : B1h, v);
                cp_async16(d + (uint32_t)(N1 * ST * 2), v ? (B1l + so) : B1l, v);
            }
            CP_COMMIT();
        };

        if (HAS_R) {
            #pragma unroll
            for (int j = 0; j < 2; j++) {
                int q = tid + j * 256;
                cp_async16(sbase + WOFF + (uint32_t)q * 16, Wrbf_g + q * 4, true);
            }
        }
        load_chunk(0, 0);
        for (int kb = 0; kb < NCH1; kb++) {
            if (kb + 1 < NCH1) { load_chunk(kb + 1, (kb + 1) & 1); cp_wait<1>(); }
            else               { cp_wait<0>(); }
            __syncthreads();

            const uint32_t sb = sbase + (uint32_t)(kb & 1) * SSZ;
            #pragma unroll
            for (int ks = 0; ks < 2; ks++) {
                uint32_t ah[2][4];
                #pragma unroll
                for (int mt = 0; mt < 2; mt++) {
                    uint32_t ea = (uint32_t)((rowA_base + mt * 16) * ST + ks * 16 + kA_off) * 2;
                    ldsm4(sb + ea, ah[mt][0], ah[mt][1], ah[mt][2], ah[mt][3]);
                }
                #pragma unroll
                for (int p = 0; p < 4; p++) {
                    uint32_t eb = (uint32_t)((rowB_base + p * 16) * ST + ks * 16 + kB_off) * 2;
                    uint32_t bh0, bh1, bh2, bh3, bl0, bl1, bl2, bl3;
                    ldsm4(sb + OFF_BH + eb, bh0, bh1, bh2, bh3);
                    ldsm4(sb + OFF_BL + eb, bl0, bl1, bl2, bl3);
                    #pragma unroll
                    for (int mt = 0; mt < 2; mt++) {
                        float* c0 = acc[mt][2 * p];
                        float* c1 = acc[mt][2 * p + 1];
                        mma_fp16(c0, ah[mt], bh0, bh1);
                        mma_fp16(c0, ah[mt], bl0, bl1);
                        mma_fp16(c1, ah[mt], bh2, bh3);
                        mma_fp16(c1, ah[mt], bl2, bl3);
                    }
                }
            }
            __syncthreads();
        }

        // preload phase-2 first B chunk into buffer 0 (B buffers idle during epilogue 1)
        loadB2(B2h, B2l, 0, 0);

        // epilogue 1: silu [* R], fp16 -> slabs
        const float2* Wsm2 = (const float2*)(smu + WOFF);
        #pragma unroll
        for (int mt = 0; mt < 2; mt++) {
            int row0 = m0 + mt * 16 + g;
            int row1 = row0 + 8;
            int gr0 = blockRow + row0, gr1 = blockRow + row1;
            float rb0[16], rb1[16];
            if (HAS_R) {
                #pragma unroll
                for (int q = 0; q < 4; q++) {
                    float4 v0 = make_float4(0.f, 0.f, 0.f, 0.f);
                    float4 v1 = make_float4(0.f, 0.f, 0.f, 0.f);
                    if (gr0 < M) v0 = *(const float4*)(rbf_g + (size_t)gr0 * 16 + q * 4);
                    if (gr1 < M) v1 = *(const float4*)(rbf_g + (size_t)gr1 * 16 + q * 4);
                    rb0[q * 4 + 0] = v0.x; rb0[q * 4 + 1] = v0.y;
                    rb0[q * 4 + 2] = v0.z; rb0[q * 4 + 3] = v0.w;
                    rb1[q * 4 + 0] = v1.x; rb1[q * 4 + 1] = v1.y;
                    rb1[q * 4 + 2] = v1.z; rb1[q * 4 + 3] = v1.w;
                }
            }
            #pragma unroll
            for (int nt = 0; nt < 8; nt++) {
                int cc = n0 + nt * 8 + 2 * t;
                float r00 = 1.f, r01 = 1.f, r10 = 1.f, r11 = 1.f;
                if (HAS_R) {
                    r00 = r01 = r10 = r11 = 0.f;
                    #pragma unroll
                    for (int k = 0; k < 16; k++) {
                        float2 w = Wsm2[k * 64 + (cc >> 1)];
                        r00 = fmaf(rb0[k], w.x, r00); r01 = fmaf(rb0[k], w.y, r01);
                        r10 = fmaf(rb1[k], w.x, r10); r11 = fmaf(rb1[k], w.y, r11);
                    }
                }
                float v00 = silu_f(acc[mt][nt][0]) * r00;
                float v01 = silu_f(acc[mt][nt][1]) * r01;
                float v10 = silu_f(acc[mt][nt][2]) * r10;
                float v11 = silu_f(acc[mt][nt][3]) * r11;
                if (gr0 >= M) { v00 = 0.f; v01 = 0.f; }
                if (gr1 >= M) { v10 = 0.f; v11 = 0.f; }
                uint32_t H0 = packh2(v00, v01);
                uint32_t H1 = packh2(v10, v11);
                uint32_t chunk = (uint32_t)(cc >> 5);
                uint32_t off0 = (uint32_t)(row0 * ST + (cc & 31)) * 2;
                uint32_t off1 = (uint32_t)(row1 * ST + (cc & 31)) * 2;
                *(uint32_t*)(smu + chunk * SLAB + off0) = H0;
                *(uint32_t*)(smu + chunk * SLAB + off1) = H1;
            }
        }
        __syncthreads();
    }

    // ======== phase 2 (+3): silu(P @ B^T) * os2 -> fp16, K = 128, double-buffered B ========
    #pragma unroll
    for (int ph = 0; ph < (THREE ? 2 : 1); ph++) {
        const __half* Bh = (ph == 0) ? B2h : B3h;
        const __half* Bl = (ph == 0) ? B2l : B3l;
        __half* outp = (ph == 0) ? out2 : out3;

        float acc2[2][NT2][4];
        #pragma unroll
        for (int mt = 0; mt < 2; mt++)
            #pragma unroll
            for (int nt = 0; nt < NT2; nt++)
                #pragma unroll
                for (int j = 0; j < 4; j++) acc2[mt][nt][j] = 0.0f;

        for (int kb = 0; kb < 4; kb++) {
            // issue next chunk (or next phase's first chunk) into the alternate buffer
            if (kb + 1 < 4) {
                loadB2(Bh, Bl, kb + 1, (kb + 1) & 1);
                cp_wait<1>();
            } else if (THREE && ph == 0) {
                loadB2(B3h, B3l, 0, 0);
                cp_wait<1>();
            } else {
                cp_wait<0>();
            }
            __syncthreads();

            const uint32_t slab = sbase + (uint32_t)kb * SLAB;
            const uint32_t bb   = sbase + B2OFF + (uint32_t)(kb & 1) * BB;
            #pragma unroll
            for (int ks = 0; ks < 2; ks++) {
                uint32_t ah[2][4];
                #pragma unroll
                for (int mt = 0; mt < 2; mt++) {
                    uint32_t ea = (uint32_t)((rowA_base + mt * 16) * ST + ks * 16 + kA_off) * 2;
                    ldsm4(slab + ea, ah[mt][0], ah[mt][1], ah[mt][2], ah[mt][3]);
                }
                #pragma unroll
                for (int p = 0; p < NPAIR2; p++) {
                    uint32_t eb = (uint32_t)((rowB2_base + p * 16) * ST + ks * 16 + kB_off) * 2;
                    uint32_t bh0, bh1, bh2, bh3, bl0, bl1, bl2, bl3;
                    ldsm4(bb + eb, bh0, bh1, bh2, bh3);
                    ldsm4(bb + (uint32_t)(N2 * ST * 2) + eb, bl0, bl1, bl2, bl3);
                    #pragma unroll
                    for (int mt = 0; mt < 2; mt++) {
                        float* c0 = acc2[mt][2 * p];
                        float* c1 = acc2[mt][2 * p + 1];
                        mma_fp16(c0, ah[mt], bh0, bh1);
                        mma_fp16(c0, ah[mt], bl0, bl1);
                        mma_fp16(c1, ah[mt], bh2, bh3);
                        mma_fp16(c1, ah[mt], bl2, bl3);
                    }
                }
            }
            __syncthreads();
        }

        #pragma unroll
        for (int mt = 0; mt < 2; mt++) {
            #pragma unroll
            for (int half = 0; half < 2; half++) {
                int r = blockRow + m0 + mt * 16 + g + half * 8;
                if (r >= M) continue;
                #pragma unroll
                for (int nt = 0; nt < NT2; nt++) {
                    int cc = n0b + nt * 8 + 2 * t;
                    float v0 = silu_f(acc2[mt][nt][half * 2 + 0]) * os2;
                    float v1 = silu_f(acc2[mt][nt][half * 2 + 1]) * os2;
                    ((uint32_t*)outp)[(size_t)r * (N2 / 2) + (cc >> 1)] = packh2(v0, v1);
                }
            }
        }
        if (THREE && ph == 0) __syncthreads();
    }
}

// ---------------- triplet (FFMA, fp16 T pre-scaled, fp16 X out) ----------------
__global__ void __launch_bounds__(256)
triplet_kernel(const __half* __restrict__ T, const float* __restrict__ cbf,
               const int* __restrict__ idx_s, const int* __restrict__ basis,
               const float* __restrict__ Wc,
               __half* __restrict__ X, int E)
{
    __shared__ float cb[8][128];
    const int warp = threadIdx.x >> 5;
    const int lane = threadIdx.x & 31;

    float w0[16], w1[16];
    #pragma unroll
    for (int c = 0; c < 16; c++) {
        w0[c] = Wc[c * 64 + 2 * lane];
        w1[c] = Wc[c * 64 + 2 * lane + 1];
    }

    const __half2* T2 = (const __half2*)T;
    const int gw = blockIdx.x * 8 + warp;
    const int nwarps = gridDim.x * 8;

    for (int e = gw; e < E; e += nwarps) {
        int s = idx_s[e];
        int b1v = 0;
        if (lane < 8) b1v = basis[s * 8 + lane];

        float4 v = *(const float4*)(cbf + (size_t)e * 128 + lane * 4);
        *(float4*)(&cb[warp][lane * 4]) = v;
        __syncwarp();

        int bidx[8];
        #pragma unroll
        for (int nb = 0; nb < 8; nb++)
            bidx[nb] = __shfl_sync(0xffffffffu, b1v, nb);

        __half2 tv[8];
        #pragma unroll
        for (int nb = 0; nb < 8; nb++)
            tv[nb] = T2[(size_t)bidx[nb] * 32 + lane];

        float acc0 = 0.f, acc1 = 0.f;
        #pragma unroll
        for (int nb = 0; nb < 8; nb++) {
            float d0 = 0.f, d1 = 0.f;
            #pragma unroll
            for (int c = 0; c < 16; c++) {
                float a = cb[warp][nb * 16 + c];
                d0 = fmaf(a, w0[c], d0);
                d1 = fmaf(a, w1[c], d1);
            }
            float2 tt = __half22float2(tv[nb]);
            acc0 = fmaf(tt.x, d0, acc0);
            acc1 = fmaf(tt.y, d1, acc1);
        }
        ((uint32_t*)X)[(size_t)e * 32 + lane] = packh2(acc0, acc1);
        __syncwarp();
    }
}

// ---------------- final elementwise: out = (XST + Z[swap]) * c ----------------
__global__ void __launch_bounds__(256)
final_ew(const __half* __restrict__ XST, const __half* __restrict__ Z,
         const int* __restrict__ swp, float* __restrict__ out, int E)
{
    size_t total = (size_t)E * 16;
    size_t stride = (size_t)gridDim.x * blockDim.x;
    for (size_t i = (size_t)blockIdx.x * blockDim.x + threadIdx.x; i < total; i += stride) {
        size_t e = i >> 4;
        int    q = (int)(i & 15);
        int    s = swp[e];
        uint4 a = ((const uint4*)XST)[i];
        uint4 b = ((const uint4*)Z)[(size_t)s * 16 + q];
        const __half2* ah = (const __half2*)&a;
        const __half2* bh = (const __half2*)&b;
        float4 o0, o1;
        float2 r0 = __half22float2(ah[0]), z0 = __half22float2(bh[0]);
        float2 r1 = __half22float2(ah[1]), z1 = __half22float2(bh[1]);
        float2 r2 = __half22float2(ah[2]), z2 = __half22float2(bh[2]);
        float2 r3 = __half22float2(ah[3]), z3 = __half22float2(bh[3]);
        o0.x = (r0.x + z0.x) * INV_SQRT_2; o0.y = (r0.y + z0.y) * INV_SQRT_2;
        o0.z = (r1.x + z1.x) * INV_SQRT_2; o0.w = (r1.y + z1.y) * INV_SQRT_2;
        o1.x = (r2.x + z2.x) * INV_SQRT_2; o1.y = (r2.y + z2.y) * INV_SQRT_2;
        o1.z = (r3.x + z3.x) * INV_SQRT_2; o1.w = (r3.y + z3.y) * INV_SQRT_2;
        ((float4*)out)[e * 32 + q * 2]     = o0;
        ((float4*)out)[e * 32 + q * 2 + 1] = o1;
    }
}

extern "C" void kernel_launch(void* const* d_in, const int* in_sizes, int n_in,
                              void* d_out, int out_size)
{
    const float* m_st     = (const float*)d_in[0];
    const float* rbf      = (const float*)d_in[1];
    const float* cbf      = (const float*)d_in[2];
    const int*   idx_s    = (const int*)d_in[3];
    const int*   idx_swap = (const int*)d_in[4];
    const int*   basis    = (const int*)d_in[5];
    const float* W_m_rbf  = (const float*)d_in[6];
    const float* W_rbf    = (const float*)d_in[7];
    const float* W_m_cbf  = (const float*)d_in[8];
    const float* W_cbf    = (const float*)d_in[9];
    const float* W_dir    = (const float*)d_in[10];
    const float* W_st     = (const float*)d_in[11];
    const float* W_ts     = (const float*)d_in[12];
    float* out = (float*)d_out;

    const int E = in_sizes[0] / DEDGE;

    __half *pT, *pZ, *pXST, *pm, *pX;
    __half *wmrh, *wmrl, *wmch, *wmcl, *wdh, *wdl, *wsth, *wstl, *wtsh, *wtsl;
    cudaGetSymbolAddress((void**)&pT,   g_T);
    cudaGetSymbolAddress((void**)&pZ,   g_Z);
    cudaGetSymbolAddress((void**)&pXST, g_XST);
    cudaGetSymbolAddress((void**)&pm,   g_mst);
    cudaGetSymbolAddress((void**)&pX,   g_X);
    cudaGetSymbolAddress((void**)&wmrh, g_Wmrh);  cudaGetSymbolAddress((void**)&wmrl, g_Wmrl);
    cudaGetSymbolAddress((void**)&wmch, g_Wmch);  cudaGetSymbolAddress((void**)&wmcl, g_Wmcl);
    cudaGetSymbolAddress((void**)&wdh,  g_Wdh);   cudaGetSymbolAddress((void**)&wdl, g_Wdl);
    cudaGetSymbolAddress((void**)&wsth, g_Wsth);  cudaGetSymbolAddress((void**)&wstl, g_Wstl);
    cudaGetSymbolAddress((void**)&wtsh, g_Wtsh);  cudaGetSymbolAddress((void**)&wtsl, g_Wtsl);

    const int gB = (E + 127) / 128;

    // smem: 2 stages (30720 each) + 2 x B buffer + optional Wrbf
    const int smem_f12 = 61440 + 2 * (2 * 64  * 40 * 2) + 8192;  // 90112
    const int smem_f45 = 61440 + 2 * (2 * 128 * 40 * 2);         // 102400

    cudaFuncSetAttribute(gemm_chain<128, 64, true, false>,
                         cudaFuncAttributeMaxDynamicSharedMemorySize, smem_f12);
    cudaFuncSetAttribute(gemm_chain<64, 128, false, true>,
                         cudaFuncAttributeMaxDynamicSharedMemorySize, smem_f45);

    // launch 0: m_st -> fp16
    conv_rows<<<(E * 64 + 255) / 256, 256>>>(m_st, pm, E * 64);
    // launch 1: split all 5 weights (fp16 hi/lo, transposed)
    {
        dim3 grid(64, 5);
        split_w_all<<<grid, 256>>>(
            W_m_rbf, wmrh, wmrl,
            W_m_cbf, wmch, wmcl,
            W_dir,   wdh,  wdl,
            W_st,    wsth, wstl,
            W_ts,    wtsh, wtsl);
    }
    // launch 2 (F12): M1 = silu(m_st@W_m_rbf)*(rbf@W_rbf) -> T(fp16, pre-scaled)
    gemm_chain<128, 64, true, false><<<gB, 256, smem_f12>>>(
        pm, wmrh, wmrl, rbf, W_rbf, wmch, wmcl, pT,
        nullptr, nullptr, nullptr, INV_SQRT_NB, E);
    // launch 3: triplet -> X fp16
    triplet_kernel<<<2048, 256>>>(pT, cbf, idx_s, basis, W_cbf, pX, E);
    // launch 4 (F45, 3-phase): Y = silu(X@W_dir) -> Z(fp16)=silu(Y@W_ts), XST(fp16)=silu(Y@W_st)
    gemm_chain<64, 128, false, true><<<gB, 256, smem_f45>>>(
        pX, wdh, wdl, nullptr, nullptr, wtsh, wtsl, pZ,
        wsth, wstl, pXST, 1.0f, E);
    // launch 5: out = (XST + Z[idx_swap]) * INV_SQRT_2
    final_ew<<<4096, 256>>>(pXST, pZ, idx_swap, out, E);
}

// round 15
// speedup vs baseline: 1.7806x; 1.0844x over previous
#include <cuda_runtime.h>
#include <cuda_fp16.h>
#include <cstdint>
#include <math.h>

#define EMAX   250000
#define DEDGE  128
#define DTRI   64

// fp16 intermediates
static __device__ __align__(16) __half g_T  [EMAX * DTRI];
static __device__ __align__(16) __half g_Z  [EMAX * DEDGE];
static __device__ __align__(16) __half g_XST[EMAX * DEDGE];
static __device__ __align__(16) __half g_X  [EMAX * DTRI];
// fp16 hi/lo transposed weights [N][K] (exact to ~2^-22)
static __device__ __align__(16) __half g_Wmrh [128 * 128], g_Wmrl [128 * 128];
static __device__ __align__(16) __half g_Wmch [64 * 128],  g_Wmcl [64 * 128];
static __device__ __align__(16) __half g_Wdh  [128 * 64],  g_Wdl  [128 * 64];
static __device__ __align__(16) __half g_Wsth [128 * 128], g_Wstl [128 * 128];
static __device__ __align__(16) __half g_Wtsh [128 * 128], g_Wtsl [128 * 128];

#define INV_SQRT_2  0.70710678118654752440f
#define INV_SQRT_NB 0.35355339059327376220f

__device__ __forceinline__ float silu_f(float x) {
    return x / (1.0f + __expf(-x));
}
__device__ __forceinline__ uint32_t smem_u32(const void* p) {
    uint32_t a;
    asm("{ .reg .u64 t; cvta.to.shared.u64 t, %1; cvt.u32.u64 %0, t; }" : "=r"(a) : "l"(p));
    return a;
}
__device__ __forceinline__ void cp_async16(uint32_t dst, const void* src, bool v) {
    int sz = v ? 16 : 0;
    asm volatile("cp.async.cg.shared.global [%0], [%1], 16, %2;"
                 :: "r"(dst), "l"(src), "r"(sz));
}
#define CP_COMMIT() asm volatile("cp.async.commit_group;" ::: "memory")
template<int n> __device__ __forceinline__ void cp_wait() {
    asm volatile("cp.async.wait_group %0;" :: "n"(n) : "memory");
}
__device__ __forceinline__ void ldsm4(uint32_t addr, uint32_t& r0, uint32_t& r1,
                                      uint32_t& r2, uint32_t& r3) {
    asm volatile("ldmatrix.sync.aligned.m8n8.x4.shared.b16 {%0,%1,%2,%3}, [%4];"
                 : "=r"(r0), "=r"(r1), "=r"(r2), "=r"(r3) : "r"(addr));
}
__device__ __forceinline__ void mma_fp16(float* c, const uint32_t* a,
                                         uint32_t b0, uint32_t b1) {
    asm volatile(
        "mma.sync.aligned.m16n8k16.row.col.f32.f16.f16.f32 "
        "{%0,%1,%2,%3}, {%4,%5,%6,%7}, {%8,%9}, {%0,%1,%2,%3};"
        : "+f"(c[0]), "+f"(c[1]), "+f"(c[2]), "+f"(c[3])
        : "r"(a[0]), "r"(a[1]), "r"(a[2]), "r"(a[3]), "r"(b0), "r"(b1));
}
__device__ __forceinline__ uint32_t packh2(float x, float y) {
    __half2 p = __floats2half2_rn(x, y);
    return *(uint32_t*)&p;
}

// ---------------- setup kernel: weight transpose-splits (one launch) ----------------
__global__ void split_w_all(
    const float* __restrict__ s0, __half* __restrict__ d0h, __half* __restrict__ d0l,
    const float* __restrict__ s1, __half* __restrict__ d1h, __half* __restrict__ d1l,
    const float* __restrict__ s2, __half* __restrict__ d2h, __half* __restrict__ d2l,
    const float* __restrict__ s3, __half* __restrict__ d3h, __half* __restrict__ d3l,
    const float* __restrict__ s4, __half* __restrict__ d4h, __half* __restrict__ d4l)
{
    int i = blockIdx.x * blockDim.x + threadIdx.x;
    int w = blockIdx.y;
    const float* src; __half *dh, *dl; int K, N;
    switch (w) {
        case 0: src = s0; dh = d0h; dl = d0l; K = 128; N = 128; break;
        case 1: src = s1; dh = d1h; dl = d1l; K = 128; N = 64;  break;
        case 2: src = s2; dh = d2h; dl = d2l; K = 64;  N = 128; break;
        case 3: src = s3; dh = d3h; dl = d3l; K = 128; N = 128; break;
        default: src = s4; dh = d4h; dl = d4l; K = 128; N = 128; break;
    }
    if (i >= K * N) return;
    int k = i / N, n = i % N;
    float v = src[i];
    __half h = __float2half(v);
    __half l = __float2half(v - __half2float(h));
    dh[n * K + k] = h;
    dl[n * K + k] = l;
}

// ---------------- chained GEMM (2 or 3 phases), fp16 A-single x fp16 B-split2 ----------------
// Phase1: P = silu(A @ B1^T) [* R(rbf@Wrbf fp32 in epilogue)] -> smem slabs (fp16)
//   AF32: A is fp32 in gmem; LDG-register-prefetched, converted, STS'd into the fp16 stage.
// Phase2: out2(fp16) = os2 * silu(P @ B2^T)
// Phase3 (if THREE): out3(fp16) = os2 * silu(P @ B3^T)
// Phases 2/3 use double-buffered B (2 buffers, one chunk ahead).
template<int K1, int N2, bool HAS_R, bool THREE, bool AF32>
__global__ void __launch_bounds__(256, 2)
gemm_chain(const float* __restrict__ Af32, const __half* __restrict__ Ah,
           const __half* __restrict__ B1h, const __half* __restrict__ B1l,
           const float* __restrict__ rbf_g, const float* __restrict__ Wrbf_g,
           const __half* __restrict__ B2h, const __half* __restrict__ B2l,
           __half* __restrict__ out2,
           const __half* __restrict__ B3h, const __half* __restrict__ B3l,
           __half* __restrict__ out3, float os2, int M)
{
    constexpr int N1  = 128;
    constexpr int ST  = 40;                                 // halfs per row
    constexpr int NCH1 = (K1 + 31) / 32;
    constexpr uint32_t OFF_BH = 128 * ST * 2;               // 10240 (A region size)
    constexpr uint32_t OFF_BL = OFF_BH + N1 * ST * 2;       // 20480
    constexpr uint32_t SSZ    = OFF_BH + 2 * N1 * ST * 2;   // 30720
    constexpr uint32_t SLAB   = 128 * ST * 2;               // 10240 per k-chunk (fp16 single)
    constexpr uint32_t B2OFF  = 2 * SSZ;                    // 61440
    constexpr uint32_t BB     = 2u * N2 * ST * 2;           // one phase-2/3 B buffer
    constexpr uint32_t WOFF   = B2OFF + 2 * BB;
    constexpr int NT2   = N2 / 16;
    constexpr int NPAIR2 = NT2 / 2;

    extern __shared__ __align__(16) char smu[];
    const uint32_t sbase = smem_u32(smu);

    const int tid  = threadIdx.x;
    const int warp = tid >> 5, lane = tid & 31;
    const int g = lane >> 2, t = lane & 3;
    const int warpM = warp & 3, warpN = warp >> 2;
    const int m0 = warpM * 32;
    const int n0 = warpN * 64;
    const int n0b = warpN * (N2 / 2);
    const int blockRow = blockIdx.x * 128;

    const int lr  = lane & 7;
    const int rowA_base = m0 + lr + ((lane >> 3) & 1) * 8;
    const int kA_off    = (lane >> 4) * 8;
    const int rowB_base = n0 + lr + (lane >> 4) * 8;
    const int rowB2_base = n0b + lr + (lane >> 4) * 8;
    const int kB_off    = ((lane >> 3) & 1) * 8;

    // phase-2/3 B chunk loader into buffer buf (commits one group)
    auto loadB2 = [&](const __half* Bh, const __half* Bl, int kb, int buf) {
        const uint32_t bb = sbase + B2OFF + (uint32_t)buf * BB;
        #pragma unroll
        for (int j = 0; j < (N2 * 4) / 256; j++) {
            int gg = tid + j * 256;
            int n = gg >> 2, q = gg & 3;
            size_t so = (size_t)n * 128 + kb * 32 + q * 8;
            uint32_t d = bb + (uint32_t)(n * ST + q * 8) * 2;
            cp_async16(d, Bh + so, true);
            cp_async16(d + (uint32_t)(N2 * ST * 2), Bl + so, true);
        }
        CP_COMMIT();
    };

    // ======== phase 1 ========
    {
        float acc[2][8][4];
        #pragma unroll
        for (int mt = 0; mt < 2; mt++)
            #pragma unroll
            for (int nt = 0; nt < 8; nt++)
                #pragma unroll
                for (int j = 0; j < 4; j++) acc[mt][nt][j] = 0.0f;

        // chunk loader: B always via cp.async; A via cp.async only when !AF32
        auto load_chunk = [&](int kb, int stage) {
            const int k0 = kb * 32;
            const uint32_t sb = sbase + (uint32_t)stage * SSZ;
            if (!AF32) {
                #pragma unroll
                for (int j = 0; j < 2; j++) {
                    int gg = tid + j * 256;
                    int row = gg >> 2, q = gg & 3;
                    bool v = (blockRow + row < M) && (k0 + q * 8 < K1);
                    size_t so = (size_t)(blockRow + row) * K1 + k0 + q * 8;
                    uint32_t d = sb + (uint32_t)(row * ST + q * 8) * 2;
                    cp_async16(d, v ? (Ah + so) : Ah, v);
                }
            }
            #pragma unroll
            for (int j = 0; j < 2; j++) {
                int gg = tid + j * 256;
                int n = gg >> 2, q = gg & 3;
                bool v = (k0 + q * 8 < K1);
                size_t so = (size_t)n * K1 + k0 + q * 8;
                uint32_t d = sb + OFF_BH + (uint32_t)(n * ST + q * 8) * 2;
                cp_async16(d, v ? (B1h + so) : B1h, v);
                cp_async16(d + (uint32_t)(N1 * ST * 2), v ? (B1l + so) : B1l, v);
            }
            CP_COMMIT();
        };

        // fp32 A register prefetch (AF32 path): 4 float4 per thread per chunk
        float4 aCur[4], aNext[4];
        auto ldgA = [&](int kb, float4* regs) {
            const int k0 = kb * 32;
            #pragma unroll
            for (int j = 0; j < 4; j++) {
                int gg = tid + j * 256;            // 1024 granules of 4 floats
                int row = gg >> 3, q = gg & 7;
                bool v = (blockRow + row < M);
                regs[j] = v ? *(const float4*)(Af32 + (size_t)(blockRow + row) * K1 + k0 + q * 4)
                            : make_float4(0.f, 0.f, 0.f, 0.f);
            }
        };
        auto stsA = [&](int stage, const float4* regs) {
            const uint32_t sb = sbase + (uint32_t)stage * SSZ;
            #pragma unroll
            for (int j = 0; j < 4; j++) {
                int gg = tid + j * 256;
                int row = gg >> 3, q = gg & 7;
                uint2 p;
                p.x = packh2(regs[j].x, regs[j].y);
                p.y = packh2(regs[j].z, regs[j].w);
                *(uint2*)((char*)smu + (sb - sbase) + (uint32_t)(row * ST + q * 4) * 2) = p;
            }
        };

        if (HAS_R) {
            #pragma unroll
            for (int j = 0; j < 2; j++) {
                int q = tid + j * 256;
                cp_async16(sbase + WOFF + (uint32_t)q * 16, Wrbf_g + q * 4, true);
            }
        }
        if (AF32) ldgA(0, aCur);
        load_chunk(0, 0);
        for (int kb = 0; kb < NCH1; kb++) {
            if (kb + 1 < NCH1) {
                if (AF32) ldgA(kb + 1, aNext);
                load_chunk(kb + 1, (kb + 1) & 1);
            }
            if (AF32) stsA(kb & 1, aCur);
            if (kb + 1 < NCH1) cp_wait<1>(); else cp_wait<0>();
            __syncthreads();

            const uint32_t sb = sbase + (uint32_t)(kb & 1) * SSZ;
            #pragma unroll
            for (int ks = 0; ks < 2; ks++) {
                uint32_t ah[2][4];
                #pragma unroll
                for (int mt = 0; mt < 2; mt++) {
                    uint32_t ea = (uint32_t)((rowA_base + mt * 16) * ST + ks * 16 + kA_off) * 2;
                    ldsm4(sb + ea, ah[mt][0], ah[mt][1], ah[mt][2], ah[mt][3]);
                }
                #pragma unroll
                for (int p = 0; p < 4; p++) {
                    uint32_t eb = (uint32_t)((rowB_base + p * 16) * ST + ks * 16 + kB_off) * 2;
                    uint32_t bh0, bh1, bh2, bh3, bl0, bl1, bl2, bl3;
                    ldsm4(sb + OFF_BH + eb, bh0, bh1, bh2, bh3);
                    ldsm4(sb + OFF_BL + eb, bl0, bl1, bl2, bl3);
                    #pragma unroll
                    for (int mt = 0; mt < 2; mt++) {
                        float* c0 = acc[mt][2 * p];
                        float* c1 = acc[mt][2 * p + 1];
                        mma_fp16(c0, ah[mt], bh0, bh1);
                        mma_fp16(c0, ah[mt], bl0, bl1);
                        mma_fp16(c1, ah[mt], bh2, bh3);
                        mma_fp16(c1, ah[mt], bl2, bl3);
                    }
                }
            }
            __syncthreads();
            if (AF32) {
                #pragma unroll
                for (int j = 0; j < 4; j++) aCur[j] = aNext[j];
            }
        }

        // preload phase-2 first B chunk into buffer 0 (B buffers idle during epilogue 1)
        loadB2(B2h, B2l, 0, 0);

        // epilogue 1: silu [* R], fp16 -> slabs
        const float2* Wsm2 = (const float2*)(smu + WOFF);
        #pragma unroll
        for (int mt = 0; mt < 2; mt++) {
            int row0 = m0 + mt * 16 + g;
            int row1 = row0 + 8;
            int gr0 = blockRow + row0, gr1 = blockRow + row1;
            float rb0[16], rb1[16];
            if (HAS_R) {
                #pragma unroll
                for (int q = 0; q < 4; q++) {
                    float4 v0 = make_float4(0.f, 0.f, 0.f, 0.f);
                    float4 v1 = make_float4(0.f, 0.f, 0.f, 0.f);
                    if (gr0 < M) v0 = *(const float4*)(rbf_g + (size_t)gr0 * 16 + q * 4);
                    if (gr1 < M) v1 = *(const float4*)(rbf_g + (size_t)gr1 * 16 + q * 4);
                    rb0[q * 4 + 0] = v0.x; rb0[q * 4 + 1] = v0.y;
                    rb0[q * 4 + 2] = v0.z; rb0[q * 4 + 3] = v0.w;
                    rb1[q * 4 + 0] = v1.x; rb1[q * 4 + 1] = v1.y;
                    rb1[q * 4 + 2] = v1.z; rb1[q * 4 + 3] = v1.w;
                }
            }
            #pragma unroll
            for (int nt = 0; nt < 8; nt++) {
                int cc = n0 + nt * 8 + 2 * t;
                float r00 = 1.f, r01 = 1.f, r10 = 1.f, r11 = 1.f;
                if (HAS_R) {
                    r00 = r01 = r10 = r11 = 0.f;
                    #pragma unroll
                    for (int k = 0; k < 16; k++) {
                        float2 w = Wsm2[k * 64 + (cc >> 1)];
                        r00 = fmaf(rb0[k], w.x, r00); r01 = fmaf(rb0[k], w.y, r01);
                        r10 = fmaf(rb1[k], w.x, r10); r11 = fmaf(rb1[k], w.y, r11);
                    }
                }
                float v00 = silu_f(acc[mt][nt][0]) * r00;
                float v01 = silu_f(acc[mt][nt][1]) * r01;
                float v10 = silu_f(acc[mt][nt][2]) * r10;
                float v11 = silu_f(acc[mt][nt][3]) * r11;
                if (gr0 >= M) { v00 = 0.f; v01 = 0.f; }
                if (gr1 >= M) { v10 = 0.f; v11 = 0.f; }
                uint32_t H0 = packh2(v00, v01);
                uint32_t H1 = packh2(v10, v11);
                uint32_t chunk = (uint32_t)(cc >> 5);
                uint32_t off0 = (uint32_t)(row0 * ST + (cc & 31)) * 2;
                uint32_t off1 = (uint32_t)(row1 * ST + (cc & 31)) * 2;
                *(uint32_t*)(smu + chunk * SLAB + off0) = H0;
                *(uint32_t*)(smu + chunk * SLAB + off1) = H1;
            }
        }
        __syncthreads();
    }

    // ======== phase 2 (+3): silu(P @ B^T) * os2 -> fp16, K = 128, double-buffered B ========
    #pragma unroll
    for (int ph = 0; ph < (THREE ? 2 : 1); ph++) {
        const __half* Bh = (ph == 0) ? B2h : B3h;
        const __half* Bl = (ph == 0) ? B2l : B3l;
        __half* outp = (ph == 0) ? out2 : out3;

        float acc2[2][NT2][4];
        #pragma unroll
        for (int mt = 0; mt < 2; mt++)
            #pragma unroll
            for (int nt = 0; nt < NT2; nt++)
                #pragma unroll
                for (int j = 0; j < 4; j++) acc2[mt][nt][j] = 0.0f;

        for (int kb = 0; kb < 4; kb++) {
            if (kb + 1 < 4) {
                loadB2(Bh, Bl, kb + 1, (kb + 1) & 1);
                cp_wait<1>();
            } else if (THREE && ph == 0) {
                loadB2(B3h, B3l, 0, 0);
                cp_wait<1>();
            } else {
                cp_wait<0>();
            }
            __syncthreads();

            const uint32_t slab = sbase + (uint32_t)kb * SLAB;
            const uint32_t bb   = sbase + B2OFF + (uint32_t)(kb & 1) * BB;
            #pragma unroll
            for (int ks = 0; ks < 2; ks++) {
                uint32_t ah[2][4];
                #pragma unroll
                for (int mt = 0; mt < 2; mt++) {
                    uint32_t ea = (uint32_t)((rowA_base + mt * 16) * ST + ks * 16 + kA_off) * 2;
                    ldsm4(slab + ea, ah[mt][0], ah[mt][1], ah[mt][2], ah[mt][3]);
                }
                #pragma unroll
                for (int p = 0; p < NPAIR2; p++) {
                    uint32_t eb = (uint32_t)((rowB2_base + p * 16) * ST + ks * 16 + kB_off) * 2;
                    uint32_t bh0, bh1, bh2, bh3, bl0, bl1, bl2, bl3;
                    ldsm4(bb + eb, bh0, bh1, bh2, bh3);
                    ldsm4(bb + (uint32_t)(N2 * ST * 2) + eb, bl0, bl1, bl2, bl3);
                    #pragma unroll
                    for (int mt = 0; mt < 2; mt++) {
                        float* c0 = acc2[mt][2 * p];
                        float* c1 = acc2[mt][2 * p + 1];
                        mma_fp16(c0, ah[mt], bh0, bh1);
                        mma_fp16(c0, ah[mt], bl0, bl1);
                        mma_fp16(c1, ah[mt], bh2, bh3);
                        mma_fp16(c1, ah[mt], bl2, bl3);
                    }
                }
            }
            __syncthreads();
        }

        #pragma unroll
        for (int mt = 0; mt < 2; mt++) {
            #pragma unroll
            for (int half = 0; half < 2; half++) {
                int r = blockRow + m0 + mt * 16 + g + half * 8;
                if (r >= M) continue;
                #pragma unroll
                for (int nt = 0; nt < NT2; nt++) {
                    int cc = n0b + nt * 8 + 2 * t;
                    float v0 = silu_f(acc2[mt][nt][half * 2 + 0]) * os2;
                    float v1 = silu_f(acc2[mt][nt][half * 2 + 1]) * os2;
                    ((uint32_t*)outp)[(size_t)r * (N2 / 2) + (cc >> 1)] = packh2(v0, v1);
                }
            }
        }
        if (THREE && ph == 0) __syncthreads();
    }
}

// ---------------- triplet (FFMA, fp16 T pre-scaled, fp16 X out) ----------------
__global__ void __launch_bounds__(256)
triplet_kernel(const __half* __restrict__ T, const float* __restrict__ cbf,
               const int* __restrict__ idx_s, const int* __restrict__ basis,
               const float* __restrict__ Wc,
               __half* __restrict__ X, int E)
{
    __shared__ float cb[8][128];
    const int warp = threadIdx.x >> 5;
    const int lane = threadIdx.x & 31;

    float w0[16], w1[16];
    #pragma unroll
    for (int c = 0; c < 16; c++) {
        w0[c] = Wc[c * 64 + 2 * lane];
        w1[c] = Wc[c * 64 + 2 * lane + 1];
    }

    const __half2* T2 = (const __half2*)T;
    const int gw = blockIdx.x * 8 + warp;
    const int nwarps = gridDim.x * 8;

    for (int e = gw; e < E; e += nwarps) {
        int s = idx_s[e];
        int b1v = 0;
        if (lane < 8) b1v = basis[s * 8 + lane];

        float4 v = *(const float4*)(cbf + (size_t)e * 128 + lane * 4);
        *(float4*)(&cb[warp][lane * 4]) = v;
        __syncwarp();

        int bidx[8];
        #pragma unroll
        for (int nb = 0; nb < 8; nb++)
            bidx[nb] = __shfl_sync(0xffffffffu, b1v, nb);

        __half2 tv[8];
        #pragma unroll
        for (int nb = 0; nb < 8; nb++)
            tv[nb] = T2[(size_t)bidx[nb] * 32 + lane];

        float acc0 = 0.f, acc1 = 0.f;
        #pragma unroll
        for (int nb = 0; nb < 8; nb++) {
            float d0 = 0.f, d1 = 0.f;
            #pragma unroll
            for (int c = 0; c < 16; c++) {
                float a = cb[warp][nb * 16 + c];
                d0 = fmaf(a, w0[c], d0);
                d1 = fmaf(a, w1[c], d1);
            }
            float2 tt = __half22float2(tv[nb]);
            acc0 = fmaf(tt.x, d0, acc0);
            acc1 = fmaf(tt.y, d1, acc1);
        }
        ((uint32_t*)X)[(size_t)e * 32 + lane] = packh2(acc0, acc1);
        __syncwarp();
    }
}

// ---------------- final elementwise: out = (XST + Z[swap]) * c ----------------
__global__ void __launch_bounds__(256)
final_ew(const __half* __restrict__ XST, const __half* __restrict__ Z,
         const int* __restrict__ swp, float* __restrict__ out, int E)
{
    size_t total = (size_t)E * 16;
    size_t stride = (size_t)gridDim.x * blockDim.x;
    for (size_t i = (size_t)blockIdx.x * blockDim.x + threadIdx.x; i < total; i += stride) {
        size_t e = i >> 4;
        int    q = (int)(i & 15);
        int    s = swp[e];
        uint4 a = ((const uint4*)XST)[i];
        uint4 b = ((const uint4*)Z)[(size_t)s * 16 + q];
        const __half2* ah = (const __half2*)&a;
        const __half2* bh = (const __half2*)&b;
        float4 o0, o1;
        float2 r0 = __half22float2(ah[0]), z0 = __half22float2(bh[0]);
        float2 r1 = __half22float2(ah[1]), z1 = __half22float2(bh[1]);
        float2 r2 = __half22float2(ah[2]), z2 = __half22float2(bh[2]);
        float2 r3 = __half22float2(ah[3]), z3 = __half22float2(bh[3]);
        o0.x = (r0.x + z0.x) * INV_SQRT_2; o0.y = (r0.y + z0.y) * INV_SQRT_2;
        o0.z = (r1.x + z1.x) * INV_SQRT_2; o0.w = (r1.y + z1.y) * INV_SQRT_2;
        o1.x = (r2.x + z2.x) * INV_SQRT_2; o1.y = (r2.y + z2.y) * INV_SQRT_2;
        o1.z = (r3.x + z3.x) * INV_SQRT_2; o1.w = (r3.y + z3.y) * INV_SQRT_2;
        ((float4*)out)[e * 32 + q * 2]     = o0;
        ((float4*)out)[e * 32 + q * 2 + 1] = o1;
    }
}

extern "C" void kernel_launch(void* const* d_in, const int* in_sizes, int n_in,
                              void* d_out, int out_size)
{
    const float* m_st     = (const float*)d_in[0];
    const float* rbf      = (const float*)d_in[1];
    const float* cbf      = (const float*)d_in[2];
    const int*   idx_s    = (const int*)d_in[3];
    const int*   idx_swap = (const int*)d_in[4];
    const int*   basis    = (const int*)d_in[5];
    const float* W_m_rbf  = (const float*)d_in[6];
    const float* W_rbf    = (const float*)d_in[7];
    const float* W_m_cbf  = (const float*)d_in[8];
    const float* W_cbf    = (const float*)d_in[9];
    const float* W_dir    = (const float*)d_in[10];
    const float* W_st     = (const float*)d_in[11];
    const float* W_ts     = (const float*)d_in[12];
    float* out = (float*)d_out;

    const int E = in_sizes[0] / DEDGE;

    __half *pT, *pZ, *pXST, *pX;
    __half *wmrh, *wmrl, *wmch, *wmcl, *wdh, *wdl, *wsth, *wstl, *wtsh, *wtsl;
    cudaGetSymbolAddress((void**)&pT,   g_T);
    cudaGetSymbolAddress((void**)&pZ,   g_Z);
    cudaGetSymbolAddress((void**)&pXST, g_XST);
    cudaGetSymbolAddress((void**)&pX,   g_X);
    cudaGetSymbolAddress((void**)&wmrh, g_Wmrh);  cudaGetSymbolAddress((void**)&wmrl, g_Wmrl);
    cudaGetSymbolAddress((void**)&wmch, g_Wmch);  cudaGetSymbolAddress((void**)&wmcl, g_Wmcl);
    cudaGetSymbolAddress((void**)&wdh,  g_Wdh);   cudaGetSymbolAddress((void**)&wdl, g_Wdl);
    cudaGetSymbolAddress((void**)&wsth, g_Wsth);  cudaGetSymbolAddress((void**)&wstl, g_Wstl);
    cudaGetSymbolAddress((void**)&wtsh, g_Wtsh);  cudaGetSymbolAddress((void**)&wtsl, g_Wtsl);

    const int gB = (E + 127) / 128;

    // smem: 2 stages (30720 each) + 2 x B buffer + optional Wrbf
    const int smem_f12 = 61440 + 2 * (2 * 64  * 40 * 2) + 8192;  // 90112
    const int smem_f45 = 61440 + 2 * (2 * 128 * 40 * 2);         // 102400

    cudaFuncSetAttribute(gemm_chain<128, 64, true, false, true>,
                         cudaFuncAttributeMaxDynamicSharedMemorySize, smem_f12);
    cudaFuncSetAttribute(gemm_chain<64, 128, false, true, false>,
                         cudaFuncAttributeMaxDynamicSharedMemorySize, smem_f45);

    // launch 0: split all 5 weights (fp16 hi/lo, transposed)
    {
        dim3 grid(64, 5);
        split_w_all<<<grid, 256>>>(
            W_m_rbf, wmrh, wmrl,
            W_m_cbf, wmch, wmcl,
            W_dir,   wdh,  wdl,
            W_st,    wsth, wstl,
            W_ts,    wtsh, wtsl);
    }
    // launch 1 (F12): M1 = silu(m_st@W_m_rbf)*(rbf@W_rbf) -> T(fp16, pre-scaled)
    //   m_st read fp32, register-converted in-kernel.
    gemm_chain<128, 64, true, false, true><<<gB, 256, smem_f12>>>(
        m_st, nullptr, wmrh, wmrl, rbf, W_rbf, wmch, wmcl, pT,
        nullptr, nullptr, nullptr, INV_SQRT_NB, E);
    // launch 2: triplet -> X fp16
    triplet_kernel<<<2048, 256>>>(pT, cbf, idx_s, basis, W_cbf, pX, E);
    // launch 3 (F45, 3-phase): Y = silu(X@W_dir) -> Z(fp16)=silu(Y@W_ts), XST(fp16)=silu(Y@W_st)
    gemm_chain<64, 128, false, true, false><<<gB, 256, smem_f45>>>(
        nullptr, pX, wdh, wdl, nullptr, nullptr, wtsh, wtsl, pZ,
        wsth, wstl, pXST, 1.0f, E);
    // launch 4: out = (XST + Z[idx_swap]) * INV_SQRT_2
    final_ew<<<4096, 256>>>(pXST, pZ, idx_swap, out, E);
}

// round 17
// speedup vs baseline: 1.9810x; 1.1126x over previous
#include <cuda_runtime.h>
#include <cuda_fp16.h>
#include <cstdint>
#include <math.h>

#define EMAX   250000
#define DEDGE  128
#define DTRI   64

// fp16 intermediates
static __device__ __align__(16) __half g_T  [EMAX * DTRI];
static __device__ __align__(16) __half g_Z  [EMAX * DEDGE];
static __device__ __align__(16) __half g_XST[EMAX * DEDGE];
static __device__ __align__(16) __half g_X  [EMAX * DTRI];
// fp16 transposed weights [N][K]
static __device__ __align__(16) __half g_Wmr [128 * 128];
static __device__ __align__(16) __half g_Wmc [64 * 128];
static __device__ __align__(16) __half g_Wd  [128 * 64];
static __device__ __align__(16) __half g_Wst [128 * 128];
static __device__ __align__(16) __half g_Wts [128 * 128];

#define INV_SQRT_2  0.70710678118654752440f
#define INV_SQRT_NB 0.35355339059327376220f

__device__ __forceinline__ float silu_f(float x) {
    return x / (1.0f + __expf(-x));
}
__device__ __forceinline__ uint32_t smem_u32(const void* p) {
    uint32_t a;
    asm("{ .reg .u64 t; cvta.to.shared.u64 t, %1; cvt.u32.u64 %0, t; }" : "=r"(a) : "l"(p));
    return a;
}
__device__ __forceinline__ void cp_async16(uint32_t dst, const void* src, bool v) {
    int sz = v ? 16 : 0;
    asm volatile("cp.async.cg.shared.global [%0], [%1], 16, %2;"
                 :: "r"(dst), "l"(src), "r"(sz));
}
#define CP_COMMIT() asm volatile("cp.async.commit_group;" ::: "memory")
template<int n> __device__ __forceinline__ void cp_wait() {
    asm volatile("cp.async.wait_group %0;" :: "n"(n) : "memory");
}
__device__ __forceinline__ void ldsm4(uint32_t addr, uint32_t& r0, uint32_t& r1,
                                      uint32_t& r2, uint32_t& r3) {
    asm volatile("ldmatrix.sync.aligned.m8n8.x4.shared.b16 {%0,%1,%2,%3}, [%4];"
                 : "=r"(r0), "=r"(r1), "=r"(r2), "=r"(r3) : "r"(addr));
}
__device__ __forceinline__ void mma_fp16(float* c, const uint32_t* a,
                                         uint32_t b0, uint32_t b1) {
    asm volatile(
        "mma.sync.aligned.m16n8k16.row.col.f32.f16.f16.f32 "
        "{%0,%1,%2,%3}, {%4,%5,%6,%7}, {%8,%9}, {%0,%1,%2,%3};"
        : "+f"(c[0]), "+f"(c[1]), "+f"(c[2]), "+f"(c[3])
        : "r"(a[0]), "r"(a[1]), "r"(a[2]), "r"(a[3]), "r"(b0), "r"(b1));
}
__device__ __forceinline__ uint32_t packh2(float x, float y) {
    __half2 p = __floats2half2_rn(x, y);
    return *(uint32_t*)&p;
}

// ---------------- setup kernel: weight transpose-converts (one launch) ----------------
__global__ void conv_w_all(
    const float* __restrict__ s0, __half* __restrict__ d0,
    const float* __restrict__ s1, __half* __restrict__ d1,
    const float* __restrict__ s2, __half* __restrict__ d2,
    const float* __restrict__ s3, __half* __restrict__ d3,
    const float* __restrict__ s4, __half* __restrict__ d4)
{
    int i = blockIdx.x * blockDim.x + threadIdx.x;
    int w = blockIdx.y;
    const float* src; __half* dst; int K, N;
    switch (w) {
        case 0: src = s0; dst = d0; K = 128; N = 128; break;
        case 1: src = s1; dst = d1; K = 128; N = 64;  break;
        case 2: src = s2; dst = d2; K = 64;  N = 128; break;
        case 3: src = s3; dst = d3; K = 128; N = 128; break;
        default: src = s4; dst = d4; K = 128; N = 128; break;
    }
    if (i >= K * N) return;
    int k = i / N, n = i % N;
    dst[n * K + k] = __float2half(src[i]);
}

// ---------------- chained GEMM (2 or 3 phases), fp16 x fp16 single ----------------
// Phase1: P = silu(A @ B1^T) [* R(rbf@Wrbf fp32 in epilogue)] -> smem slabs (fp16)
//   AF32: A is fp32 in gmem; LDG-register-prefetched, converted, STS'd into the fp16 stage.
// Phase2: out2(fp16) = os2 * silu(P @ B2^T)
// Phase3 (if THREE): out3(fp16) = os2 * silu(P @ B3^T)
// Phases 2/3 use double-buffered B (2 buffers, one chunk ahead).
template<int K1, int N2, bool HAS_R, bool THREE, bool AF32>
__global__ void __launch_bounds__(256, 2)
gemm_chain(const float* __restrict__ Af32, const __half* __restrict__ Ah,
           const __half* __restrict__ B1,
           const float* __restrict__ rbf_g, const float* __restrict__ Wrbf_g,
           const __half* __restrict__ B2, __half* __restrict__ out2,
           const __half* __restrict__ B3, __half* __restrict__ out3,
           float os2, int M)
{
    constexpr int N1  = 128;
    constexpr int ST  = 40;                                 // halfs per row
    constexpr int NCH1 = (K1 + 31) / 32;
    constexpr uint32_t OFF_BH = 128 * ST * 2;               // 10240 (A region size)
    constexpr uint32_t SSZ    = OFF_BH + N1 * ST * 2;       // 20480
    constexpr uint32_t SLAB   = 128 * ST * 2;               // 10240 per k-chunk
    constexpr uint32_t B2OFF  = 2 * SSZ;                    // 40960
    constexpr uint32_t BB     = (uint32_t)N2 * ST * 2;      // one phase-2/3 B buffer
    constexpr uint32_t WOFF   = B2OFF + 2 * BB;
    constexpr int NT2   = N2 / 16;
    constexpr int NPAIR2 = NT2 / 2;

    extern __shared__ __align__(16) char smu[];
    const uint32_t sbase = smem_u32(smu);

    const int tid  = threadIdx.x;
    const int warp = tid >> 5, lane = tid & 31;
    const int g = lane >> 2, t = lane & 3;
    const int warpM = warp & 3, warpN = warp >> 2;
    const int m0 = warpM * 32;
    const int n0 = warpN * 64;
    const int n0b = warpN * (N2 / 2);
    const int blockRow = blockIdx.x * 128;

    const int lr  = lane & 7;
    const int rowA_base = m0 + lr + ((lane >> 3) & 1) * 8;
    const int kA_off    = (lane >> 4) * 8;
    const int rowB_base = n0 + lr + (lane >> 4) * 8;
    const int rowB2_base = n0b + lr + (lane >> 4) * 8;
    const int kB_off    = ((lane >> 3) & 1) * 8;

    // phase-2/3 B chunk loader into buffer buf (commits one group)
    // granules = N2 rows x 4 (each granule = 8 halfs of the 32-half chunk row)
    auto loadB2 = [&](const __half* B, int kb, int buf) {
        const uint32_t bb = sbase + B2OFF + (uint32_t)buf * BB;
        #pragma unroll
        for (int j = 0; j < (N2 * 4) / 256; j++) {
            int gg = tid + j * 256;
            int n = gg >> 2, q = gg & 3;
            size_t so = (size_t)n * 128 + kb * 32 + q * 8;
            uint32_t d = bb + (uint32_t)(n * ST + q * 8) * 2;
            cp_async16(d, B + so, true);
        }
        CP_COMMIT();
    };

    // ======== phase 1 ========
    {
        float acc[2][8][4];
        #pragma unroll
        for (int mt = 0; mt < 2; mt++)
            #pragma unroll
            for (int nt = 0; nt < 8; nt++)
                #pragma unroll
                for (int j = 0; j < 4; j++) acc[mt][nt][j] = 0.0f;

        // chunk loader: B via cp.async; A via cp.async only when !AF32
        auto load_chunk = [&](int kb, int stage) {
            const int k0 = kb * 32;
            const uint32_t sb = sbase + (uint32_t)stage * SSZ;
            if (!AF32) {
                #pragma unroll
                for (int j = 0; j < 2; j++) {
                    int gg = tid + j * 256;
                    int row = gg >> 2, q = gg & 3;
                    bool v = (blockRow + row < M) && (k0 + q * 8 < K1);
                    size_t so = (size_t)(blockRow + row) * K1 + k0 + q * 8;
                    uint32_t d = sb + (uint32_t)(row * ST + q * 8) * 2;
                    cp_async16(d, v ? (Ah + so) : Ah, v);
                }
            }
            #pragma unroll
            for (int j = 0; j < 2; j++) {
                int gg = tid + j * 256;
                int n = gg >> 2, q = gg & 3;
                bool v = (k0 + q * 8 < K1);
                size_t so = (size_t)n * K1 + k0 + q * 8;
                uint32_t d = sb + OFF_BH + (uint32_t)(n * ST + q * 8) * 2;
                cp_async16(d, v ? (B1 + so) : B1, v);
            }
            CP_COMMIT();
        };

        // fp32 A register prefetch (AF32 path): 4 float4 per thread per chunk
        float4 aCur[4], aNext[4];
        auto ldgA = [&](int kb, float4* regs) {
            const int k0 = kb * 32;
            #pragma unroll
            for (int j = 0; j < 4; j++) {
                int gg = tid + j * 256;
                int row = gg >> 3, q = gg & 7;
                bool v = (blockRow + row < M);
                regs[j] = v ? *(const float4*)(Af32 + (size_t)(blockRow + row) * K1 + k0 + q * 4)
                            : make_float4(0.f, 0.f, 0.f, 0.f);
            }
        };
        auto stsA = [&](int stage, const float4* regs) {
            const uint32_t sb = sbase + (uint32_t)stage * SSZ;
            #pragma unroll
            for (int j = 0; j < 4; j++) {
                int gg = tid + j * 256;
                int row = gg >> 3, q = gg & 7;
                uint2 p;
                p.x = packh2(regs[j].x, regs[j].y);
                p.y = packh2(regs[j].z, regs[j].w);
                *(uint2*)((char*)smu + (sb - sbase) + (uint32_t)(row * ST + q * 4) * 2) = p;
            }
        };

        if (HAS_R) {
            #pragma unroll
            for (int j = 0; j < 2; j++) {
                int q = tid + j * 256;
                cp_async16(sbase + WOFF + (uint32_t)q * 16, Wrbf_g + q * 4, true);
            }
        }
        if (AF32) ldgA(0, aCur);
        load_chunk(0, 0);
        for (int kb = 0; kb < NCH1; kb++) {
            if (kb + 1 < NCH1) {
                if (AF32) ldgA(kb + 1, aNext);
                load_chunk(kb + 1, (kb + 1) & 1);
            }
            if (AF32) stsA(kb & 1, aCur);
            if (kb + 1 < NCH1) cp_wait<1>(); else cp_wait<0>();
            __syncthreads();

            const uint32_t sb = sbase + (uint32_t)(kb & 1) * SSZ;
            #pragma unroll
            for (int ks = 0; ks < 2; ks++) {
                uint32_t ah[2][4];
                #pragma unroll
                for (int mt = 0; mt < 2; mt++) {
                    uint32_t ea = (uint32_t)((rowA_base + mt * 16) * ST + ks * 16 + kA_off) * 2;
                    ldsm4(sb + ea, ah[mt][0], ah[mt][1], ah[mt][2], ah[mt][3]);
                }
                #pragma unroll
                for (int p = 0; p < 4; p++) {
                    uint32_t eb = (uint32_t)((rowB_base + p * 16) * ST + ks * 16 + kB_off) * 2;
                    uint32_t bh0, bh1, bh2, bh3;
                    ldsm4(sb + OFF_BH + eb, bh0, bh1, bh2, bh3);
                    #pragma unroll
                    for (int mt = 0; mt < 2; mt++) {
                        mma_fp16(acc[mt][2 * p],     ah[mt], bh0, bh1);
                        mma_fp16(acc[mt][2 * p + 1], ah[mt], bh2, bh3);
                    }
                }
            }
            __syncthreads();
            if (AF32) {
                #pragma unroll
                for (int j = 0; j < 4; j++) aCur[j] = aNext[j];
            }
        }

        // preload phase-2 first B chunk into buffer 0 (B buffers idle during epilogue 1)
        loadB2(B2, 0, 0);

        // epilogue 1: silu [* R], fp16 -> slabs
        const float2* Wsm2 = (const float2*)(smu + WOFF);
        #pragma unroll
        for (int mt = 0; mt < 2; mt++) {
            int row0 = m0 + mt * 16 + g;
            int row1 = row0 + 8;
            int gr0 = blockRow + row0, gr1 = blockRow + row1;
            float rb0[16], rb1[16];
            if (HAS_R) {
                #pragma unroll
                for (int q = 0; q < 4; q++) {
                    float4 v0 = make_float4(0.f, 0.f, 0.f, 0.f);
                    float4 v1 = make_float4(0.f, 0.f, 0.f, 0.f);
                    if (gr0 < M) v0 = *(const float4*)(rbf_g + (size_t)gr0 * 16 + q * 4);
                    if (gr1 < M) v1 = *(const float4*)(rbf_g + (size_t)gr1 * 16 + q * 4);
                    rb0[q * 4 + 0] = v0.x; rb0[q * 4 + 1] = v0.y;
                    rb0[q * 4 + 2] = v0.z; rb0[q * 4 + 3] = v0.w;
                    rb1[q * 4 + 0] = v1.x; rb1[q * 4 + 1] = v1.y;
                    rb1[q * 4 + 2] = v1.z; rb1[q * 4 + 3] = v1.w;
                }
            }
            #pragma unroll
            for (int nt = 0; nt < 8; nt++) {
                int cc = n0 + nt * 8 + 2 * t;
                float r00 = 1.f, r01 = 1.f, r10 = 1.f, r11 = 1.f;
                if (HAS_R) {
                    r00 = r01 = r10 = r11 = 0.f;
                    #pragma unroll
                    for (int k = 0; k < 16; k++) {
                        float2 w = Wsm2[k * 64 + (cc >> 1)];
                        r00 = fmaf(rb0[k], w.x, r00); r01 = fmaf(rb0[k], w.y, r01);
                        r10 = fmaf(rb1[k], w.x, r10); r11 = fmaf(rb1[k], w.y, r11);
                    }
                }
                float v00 = silu_f(acc[mt][nt][0]) * r00;
                float v01 = silu_f(acc[mt][nt][1]) * r01;
                float v10 = silu_f(acc[mt][nt][2]) * r10;
                float v11 = silu_f(acc[mt][nt][3]) * r11;
                if (gr0 >= M) { v00 = 0.f; v01 = 0.f; }
                if (gr1 >= M) { v10 = 0.f; v11 = 0.f; }
                uint32_t H0 = packh2(v00, v01);
                uint32_t H1 = packh2(v10, v11);
                uint32_t chunk = (uint32_t)(cc >> 5);
                uint32_t off0 = (uint32_t)(row0 * ST + (cc & 31)) * 2;
                uint32_t off1 = (uint32_t)(row1 * ST + (cc & 31)) * 2;
                *(uint32_t*)(smu + chunk * SLAB + off0) = H0;
                *(uint32_t*)(smu + chunk * SLAB + off1) = H1;
            }
        }
        __syncthreads();
    }

    // ======== phase 2 (+3): silu(P @ B^T) * os2 -> fp16, K = 128, double-buffered B ========
    #pragma unroll
    for (int ph = 0; ph < (THREE ? 2 : 1); ph++) {
        const __half* B = (ph == 0) ? B2 : B3;
        __half* outp = (ph == 0) ? out2 : out3;

        float acc2[2][NT2][4];
        #pragma unroll
        for (int mt = 0; mt < 2; mt++)
            #pragma unroll
            for (int nt = 0; nt < NT2; nt++)
                #pragma unroll
                for (int j = 0; j < 4; j++) acc2[mt][nt][j] = 0.0f;

        for (int kb = 0; kb < 4; kb++) {
            if (kb + 1 < 4) {
                loadB2(B, kb + 1, (kb + 1) & 1);
                cp_wait<1>();
            } else if (THREE && ph == 0) {
                loadB2(B3, 0, 0);
                cp_wait<1>();
            } else {
                cp_wait<0>();
            }
            __syncthreads();

            const uint32_t slab = sbase + (uint32_t)kb * SLAB;
            const uint32_t bb   = sbase + B2OFF + (uint32_t)(kb & 1) * BB;
            #pragma unroll
            for (int ks = 0; ks < 2; ks++) {
                uint32_t ah[2][4];
                #pragma unroll
                for (int mt = 0; mt < 2; mt++) {
                    uint32_t ea = (uint32_t)((rowA_base + mt * 16) * ST + ks * 16 + kA_off) * 2;
                    ldsm4(slab + ea, ah[mt][0], ah[mt][1], ah[mt][2], ah[mt][3]);
                }
                #pragma unroll
                for (int p = 0; p < NPAIR2; p++) {
                    uint32_t eb = (uint32_t)((rowB2_base + p * 16) * ST + ks * 16 + kB_off) * 2;
                    uint32_t bh0, bh1, bh2, bh3;
                    ldsm4(bb + eb, bh0, bh1, bh2, bh3);
                    #pragma unroll
                    for (int mt = 0; mt < 2; mt++) {
                        mma_fp16(acc2[mt][2 * p],     ah[mt], bh0, bh1);
                        mma_fp16(acc2[mt][2 * p + 1], ah[mt], bh2, bh3);
                    }
                }
            }
            __syncthreads();
        }

        #pragma unroll
        for (int mt = 0; mt < 2; mt++) {
            #pragma unroll
            for (int half = 0; half < 2; half++) {
                int r = blockRow + m0 + mt * 16 + g + half * 8;
                if (r >= M) continue;
                #pragma unroll
                for (int nt = 0; nt < NT2; nt++) {
                    int cc = n0b + nt * 8 + 2 * t;
                    float v0 = silu_f(acc2[mt][nt][half * 2 + 0]) * os2;
                    float v1 = silu_f(acc2[mt][nt][half * 2 + 1]) * os2;
                    ((uint32_t*)outp)[(size_t)r * (N2 / 2) + (cc >> 1)] = packh2(v0, v1);
                }
            }
        }
        if (THREE && ph == 0) __syncthreads();
    }
}

// ---------------- triplet (FFMA, fp16 T pre-scaled, fp16 X out) ----------------
__global__ void __launch_bounds__(256)
triplet_kernel(const __half* __restrict__ T, const float* __restrict__ cbf,
               const int* __restrict__ idx_s, const int* __restrict__ basis,
               const float* __restrict__ Wc,
               __half* __restrict__ X, int E)
{
    __shared__ float cb[8][128];
    const int warp = threadIdx.x >> 5;
    const int lane = threadIdx.x & 31;

    float w0[16], w1[16];
    #pragma unroll
    for (int c = 0; c < 16; c++) {
        w0[c] = Wc[c * 64 + 2 * lane];
        w1[c] = Wc[c * 64 + 2 * lane + 1];
    }

    const __half2* T2 = (const __half2*)T;
    const int gw = blockIdx.x * 8 + warp;
    const int nwarps = gridDim.x * 8;

    for (int e = gw; e < E; e += nwarps) {
        int s = idx_s[e];
        int b1v = 0;
        if (lane < 8) b1v = basis[s * 8 + lane];

        float4 v = *(const float4*)(cbf + (size_t)e * 128 + lane * 4);
        *(float4*)(&cb[warp][lane * 4]) = v;
        __syncwarp();

        int bidx[8];
        #pragma unroll
        for (int nb = 0; nb < 8; nb++)
            bidx[nb] = __shfl_sync(0xffffffffu, b1v, nb);

        __half2 tv[8];
        #pragma unroll
        for (int nb = 0; nb < 8; nb++)
            tv[nb] = T2[(size_t)bidx[nb] * 32 + lane];

        float acc0 = 0.f, acc1 = 0.f;
        #pragma unroll
        for (int nb = 0; nb < 8; nb++) {
            float d0 = 0.f, d1 = 0.f;
            #pragma unroll
            for (int c = 0; c < 16; c++) {
                float a = cb[warp][nb * 16 + c];
                d0 = fmaf(a, w0[c], d0);
                d1 = fmaf(a, w1[c], d1);
            }
            float2 tt = __half22float2(tv[nb]);
            acc0 = fmaf(tt.x, d0, acc0);
            acc1 = fmaf(tt.y, d1, acc1);
        }
        ((uint32_t*)X)[(size_t)e * 32 + lane] = packh2(acc0, acc1);
        __syncwarp();
    }
}

// ---------------- final elementwise: out = (XST + Z[swap]) * c ----------------
__global__ void __launch_bounds__(256)
final_ew(const __half* __restrict__ XST, const __half* __restrict__ Z,
         const int* __restrict__ swp, float* __restrict__ out, int E)
{
    size_t total = (size_t)E * 16;
    size_t stride = (size_t)gridDim.x * blockDim.x;
    for (size_t i = (size_t)blockIdx.x * blockDim.x + threadIdx.x; i < total; i += stride) {
        size_t e = i >> 4;
        int    q = (int)(i & 15);
        int    s = swp[e];
        uint4 a = ((const uint4*)XST)[i];
        uint4 b = ((const uint4*)Z)[(size_t)s * 16 + q];
        const __half2* ah = (const __half2*)&a;
        const __half2* bh = (const __half2*)&b;
        float4 o0, o1;
        float2 r0 = __half22float2(ah[0]), z0 = __half22float2(bh[0]);
        float2 r1 = __half22float2(ah[1]), z1 = __half22float2(bh[1]);
        float2 r2 = __half22float2(ah[2]), z2 = __half22float2(bh[2]);
        float2 r3 = __half22float2(ah[3]), z3 = __half22float2(bh[3]);
        o0.x = (r0.x + z0.x) * INV_SQRT_2; o0.y = (r0.y + z0.y) * INV_SQRT_2;
        o0.z = (r1.x + z1.x) * INV_SQRT_2; o0.w = (r1.y + z1.y) * INV_SQRT_2;
        o1.x = (r2.x + z2.x) * INV_SQRT_2; o1.y = (r2.y + z2.y) * INV_SQRT_2;
        o1.z = (r3.x + z3.x) * INV_SQRT_2; o1.w = (r3.y + z3.y) * INV_SQRT_2;
        ((float4*)out)[e * 32 + q * 2]     = o0;
        ((float4*)out)[e * 32 + q * 2 + 1] = o1;
    }
}

extern "C" void kernel_launch(void* const* d_in, const int* in_sizes, int n_in,
                              void* d_out, int out_size)
{
    const float* m_st     = (const float*)d_in[0];
    const float* rbf      = (const float*)d_in[1];
    const float* cbf      = (const float*)d_in[2];
    const int*   idx_s    = (const int*)d_in[3];
    const int*   idx_swap = (const int*)d_in[4];
    const int*   basis    = (const int*)d_in[5];
    const float* W_m_rbf  = (const float*)d_in[6];
    const float* W_rbf    = (const float*)d_in[7];
    const float* W_m_cbf  = (const float*)d_in[8];
    const float* W_cbf    = (const float*)d_in[9];
    const float* W_dir    = (const float*)d_in[10];
    const float* W_st     = (const float*)d_in[11];
    const float* W_ts     = (const float*)d_in[12];
    float* out = (float*)d_out;

    const int E = in_sizes[0] / DEDGE;

    __half *pT, *pZ, *pXST, *pX;
    __half *wmr, *wmc, *wd, *wst, *wts;
    cudaGetSymbolAddress((void**)&pT,   g_T);
    cudaGetSymbolAddress((void**)&pZ,   g_Z);
    cudaGetSymbolAddress((void**)&pXST, g_XST);
    cudaGetSymbolAddress((void**)&pX,   g_X);
    cudaGetSymbolAddress((void**)&wmr, g_Wmr);
    cudaGetSymbolAddress((void**)&wmc, g_Wmc);
    cudaGetSymbolAddress((void**)&wd,  g_Wd);
    cudaGetSymbolAddress((void**)&wst, g_Wst);
    cudaGetSymbolAddress((void**)&wts, g_Wts);

    const int gB = (E + 127) / 128;

    // smem: 2 stages (20480 each) + 2 x B buffer + optional Wrbf
    const int smem_f12 = 40960 + 2 * (64  * 40 * 2) + 8192;  // 59392
    const int smem_f45 = 40960 + 2 * (128 * 40 * 2);         // 61440

    cudaFuncSetAttribute(gemm_chain<128, 64, true, false, true>,
                         cudaFuncAttributeMaxDynamicSharedMemorySize, smem_f12);
    cudaFuncSetAttribute(gemm_chain<64, 128, false, true, false>,
                         cudaFuncAttributeMaxDynamicSharedMemorySize, smem_f45);

    // launch 0: convert all 5 weights (fp16, transposed)
    {
        dim3 grid(64, 5);
        conv_w_all<<<grid, 256>>>(
            W_m_rbf, wmr,
            W_m_cbf, wmc,
            W_dir,   wd,
            W_st,    wst,
            W_ts,    wts);
    }
    // launch 1 (F12): M1 = silu(m_st@W_m_rbf)*(rbf@W_rbf) -> T(fp16, pre-scaled)
    gemm_chain<128, 64, true, false, true><<<gB, 256, smem_f12>>>(
        m_st, nullptr, wmr, rbf, W_rbf, wmc, pT,
        nullptr, nullptr, INV_SQRT_NB, E);
    // launch 2: triplet -> X fp16
    triplet_kernel<<<2048, 256>>>(pT, cbf, idx_s, basis, W_cbf, pX, E);
    // launch 3 (F45, 3-phase): Y = silu(X@W_dir) -> Z(fp16)=silu(Y@W_ts), XST(fp16)=silu(Y@W_st)
    gemm_chain<64, 128, false, true, false><<<gB, 256, smem_f45>>>(
        nullptr, pX, wd, nullptr, nullptr, wts, pZ,
        wst, pXST, 1.0f, E);
    // launch 4: out = (XST + Z[idx_swap]) * INV_SQRT_2
    final_ew<<<4096, 256>>>(pXST, pZ, idx_swap, out, E);
}